// round 1
// baseline (speedup 1.0000x reference)
#include <cuda_runtime.h>
#include <math.h>

// Problem constants
#define S_LEN 2048
#define BATCHN 2
#define DM 1024
#define NHEAD 16
#define DHEAD 64
#define MROWS (BATCHN * S_LEN)   // 4096

// Scratch (device globals: allocation-free rule)
__device__ float g_qkv[(size_t)3 * MROWS * DM];   // [3][M][D] : Q, K, V in [b*S+s, h*64+dh] layout
__device__ float g_att[(size_t)MROWS * DM];       // attention output, [b*S+s, h*64+dh]

// ---------------------------------------------------------------------------
// NT SGEMM: C[m,n] = sum_k A[m,k] * W[n,k]
// A: [MROWS, DM] row-major. W: [DM, DM] row-major (d_out, d_in).
// Mode 1 (C_ext == nullptr): A = A_ext (x), W chosen by blockIdx.z from W0/W1/W2,
//                            C = g_qkv + z*M*N  (QKV projection, grid.z = 3)
// Mode 2 (C_ext != nullptr): A = g_att, W = W0, C = C_ext (output projection)
// Tiling: BM=BN=128, BK=8, TM=TN=8, 256 threads.
// ---------------------------------------------------------------------------
#define GBM 128
#define GBN 128
#define GBK 8
#define GTM 8
#define GTN 8

__global__ void __launch_bounds__(256, 2)
sgemm_nt(const float* __restrict__ A_ext,
         const float* __restrict__ W0,
         const float* __restrict__ W1,
         const float* __restrict__ W2,
         float* __restrict__ C_ext)
{
    __shared__ float As[GBK][GBM];
    __shared__ float Bs[GBK][GBN];

    const int z = blockIdx.z;
    const float* W = (z == 0) ? W0 : ((z == 1) ? W1 : W2);
    const float* A = (C_ext == nullptr) ? A_ext : g_att;
    float* C = (C_ext == nullptr) ? (g_qkv + (size_t)z * MROWS * DM) : C_ext;

    const int tid = threadIdx.x;
    const int m0 = blockIdx.y * GBM;
    const int n0 = blockIdx.x * GBN;

    // Global load mapping: 128 rows x 8 k-cols = 256 float4; 1 per thread per operand
    const int a_row = tid >> 1;          // 0..127
    const int a_kq  = (tid & 1) * 4;     // 0 or 4

    const float* Aptr = A + (size_t)(m0 + a_row) * DM + a_kq;
    const float* Wptr = W + (size_t)(n0 + a_row) * DM + a_kq;

    // Compute mapping
    const int tr = (tid >> 4) * GTM;     // 0..120
    const int tc = (tid & 15) * GTN;     // 0..120

    float acc[GTM][GTN];
#pragma unroll
    for (int i = 0; i < GTM; i++)
#pragma unroll
        for (int j = 0; j < GTN; j++) acc[i][j] = 0.f;

    for (int k0 = 0; k0 < DM; k0 += GBK) {
        float4 av = *(const float4*)(Aptr + k0);
        float4 bv = *(const float4*)(Wptr + k0);
        As[a_kq + 0][a_row] = av.x;
        As[a_kq + 1][a_row] = av.y;
        As[a_kq + 2][a_row] = av.z;
        As[a_kq + 3][a_row] = av.w;
        Bs[a_kq + 0][a_row] = bv.x;
        Bs[a_kq + 1][a_row] = bv.y;
        Bs[a_kq + 2][a_row] = bv.z;
        Bs[a_kq + 3][a_row] = bv.w;
        __syncthreads();

#pragma unroll
        for (int k = 0; k < GBK; k++) {
            float aF[GTM], bF[GTN];
            *(float4*)&aF[0] = *(const float4*)&As[k][tr];
            *(float4*)&aF[4] = *(const float4*)&As[k][tr + 4];
            *(float4*)&bF[0] = *(const float4*)&Bs[k][tc];
            *(float4*)&bF[4] = *(const float4*)&Bs[k][tc + 4];
#pragma unroll
            for (int i = 0; i < GTM; i++)
#pragma unroll
                for (int j = 0; j < GTN; j++)
                    acc[i][j] = fmaf(aF[i], bF[j], acc[i][j]);
        }
        __syncthreads();
    }

#pragma unroll
    for (int i = 0; i < GTM; i++) {
        float* crow = C + (size_t)(m0 + tr + i) * DM + n0 + tc;
        *(float4*)&crow[0] = make_float4(acc[i][0], acc[i][1], acc[i][2], acc[i][3]);
        *(float4*)&crow[4] = make_float4(acc[i][4], acc[i][5], acc[i][6], acc[i][7]);
    }
}

// ---------------------------------------------------------------------------
// Causal flash attention, fp32. One block per (query tile of 64, b*h).
// 128 threads: ty = tid/8 (16 row groups of 4 rows), tx = tid%8 (8 col groups of 8).
// smem: Qt [d][r] 16KB, Kt [d][c] 16KB (reused as Pt [c][r]), V [n][d] 16KB = 48KB.
// ---------------------------------------------------------------------------
__global__ void __launch_bounds__(128, 4)
flash_attn(void)
{
    __shared__ float sQt[DHEAD * 64];   // [d][r]
    __shared__ float sKt[DHEAD * 64];   // [d][c], reused as Pt [c][r]
    __shared__ float sV [64 * DHEAD];   // [n][d]

    const int qi = (gridDim.x - 1) - blockIdx.x;   // big tiles first
    const int bh = blockIdx.y;
    const int b  = bh >> 4;
    const int h  = bh & 15;

    const size_t MN = (size_t)MROWS * DM;
    const float* Q  = g_qkv +          (size_t)b * S_LEN * DM + h * DHEAD;
    const float* Kp = g_qkv + MN     + (size_t)b * S_LEN * DM + h * DHEAD;
    const float* Vp = g_qkv + 2 * MN + (size_t)b * S_LEN * DM + h * DHEAD;

    const int tid = threadIdx.x;
    const int ty = tid >> 3;   // 0..15, rows ty*4 .. ty*4+3
    const int tx = tid & 7;    // 0..7,  cols tx*8 .. tx*8+7

    // Load Q tile (64 rows x 64 d), transposed into sQt[d][r]
#pragma unroll
    for (int i = 0; i < 8; i++) {
        int p = tid + i * 128;         // float4 index in [0,1024)
        int r = p >> 4;
        int d = (p & 15) * 4;
        float4 v = *(const float4*)(Q + (size_t)(qi * 64 + r) * DM + d);
        sQt[(d + 0) * 64 + r] = v.x;
        sQt[(d + 1) * 64 + r] = v.y;
        sQt[(d + 2) * 64 + r] = v.z;
        sQt[(d + 3) * 64 + r] = v.w;
    }

    float m_i[4], l_i[4], o[4][8];
#pragma unroll
    for (int rr = 0; rr < 4; rr++) {
        m_i[rr] = -1e30f;
        l_i[rr] = 0.f;
#pragma unroll
        for (int cc = 0; cc < 8; cc++) o[rr][cc] = 0.f;
    }

    for (int j = 0; j <= qi; j++) {
        __syncthreads();   // prev iter done reading Pt(sKt)/sV; Q-store visible on first iter after next sync
        // Load K tile transposed -> sKt[d][c];  V tile natural -> sV[n][d]
#pragma unroll
        for (int i = 0; i < 8; i++) {
            int p = tid + i * 128;
            int r = p >> 4;
            int d = (p & 15) * 4;
            float4 kv = *(const float4*)(Kp + (size_t)(j * 64 + r) * DM + d);
            sKt[(d + 0) * 64 + r] = kv.x;
            sKt[(d + 1) * 64 + r] = kv.y;
            sKt[(d + 2) * 64 + r] = kv.z;
            sKt[(d + 3) * 64 + r] = kv.w;
            float4 vv = *(const float4*)(Vp + (size_t)(j * 64 + r) * DM + d);
            *(float4*)&sV[r * 64 + d] = vv;
        }
        __syncthreads();

        // Scores: s[rr][cc] = sum_d Q[r,d] K[c,d]
        float s[4][8];
#pragma unroll
        for (int rr = 0; rr < 4; rr++)
#pragma unroll
            for (int cc = 0; cc < 8; cc++) s[rr][cc] = 0.f;

#pragma unroll 8
        for (int d = 0; d < DHEAD; d++) {
            float aF[4], bF[8];
            *(float4*)&aF[0] = *(const float4*)&sQt[d * 64 + ty * 4];
            *(float4*)&bF[0] = *(const float4*)&sKt[d * 64 + tx * 8];
            *(float4*)&bF[4] = *(const float4*)&sKt[d * 64 + tx * 8 + 4];
#pragma unroll
            for (int rr = 0; rr < 4; rr++)
#pragma unroll
                for (int cc = 0; cc < 8; cc++)
                    s[rr][cc] = fmaf(aF[rr], bF[cc], s[rr][cc]);
        }

        const float scale = 0.125f;   // 1/sqrt(64)
        if (j == qi) {
#pragma unroll
            for (int rr = 0; rr < 4; rr++)
#pragma unroll
                for (int cc = 0; cc < 8; cc++) {
                    int r = ty * 4 + rr, c = tx * 8 + cc;
                    s[rr][cc] = (c <= r) ? s[rr][cc] * scale : -1e30f;
                }
        } else {
#pragma unroll
            for (int rr = 0; rr < 4; rr++)
#pragma unroll
                for (int cc = 0; cc < 8; cc++) s[rr][cc] *= scale;
        }

        // Online softmax per row (8 tx-lanes share a row)
        float p[4][8], corr[4], rsum[4];
#pragma unroll
        for (int rr = 0; rr < 4; rr++) {
            float tm = s[rr][0];
#pragma unroll
            for (int cc = 1; cc < 8; cc++) tm = fmaxf(tm, s[rr][cc]);
#pragma unroll
            for (int msk = 1; msk < 8; msk <<= 1)
                tm = fmaxf(tm, __shfl_xor_sync(0xffffffffu, tm, msk));
            float mnew = fmaxf(m_i[rr], tm);
            corr[rr] = __expf(m_i[rr] - mnew);
            m_i[rr] = mnew;
            float ls = 0.f;
#pragma unroll
            for (int cc = 0; cc < 8; cc++) {
                p[rr][cc] = __expf(s[rr][cc] - mnew);
                ls += p[rr][cc];
            }
#pragma unroll
            for (int msk = 1; msk < 8; msk <<= 1)
                ls += __shfl_xor_sync(0xffffffffu, ls, msk);
            rsum[rr] = ls;
        }

        __syncthreads();   // all threads done reading sKt as K before overwriting with Pt

        // Store Pt[c][r] into sKt region; rescale O; update l
#pragma unroll
        for (int rr = 0; rr < 4; rr++) {
            l_i[rr] = l_i[rr] * corr[rr] + rsum[rr];
#pragma unroll
            for (int cc = 0; cc < 8; cc++) {
                o[rr][cc] *= corr[rr];
                sKt[(tx * 8 + cc) * 64 + (ty * 4 + rr)] = p[rr][cc];
            }
        }
        __syncthreads();

        // O[r,d] += sum_n P[r,n] V[n,d]
#pragma unroll 8
        for (int n = 0; n < 64; n++) {
            float pF[4], vF[8];
            *(float4*)&pF[0] = *(const float4*)&sKt[n * 64 + ty * 4];
            *(float4*)&vF[0] = *(const float4*)&sV[n * 64 + tx * 8];
            *(float4*)&vF[4] = *(const float4*)&sV[n * 64 + tx * 8 + 4];
#pragma unroll
            for (int rr = 0; rr < 4; rr++)
#pragma unroll
                for (int cc = 0; cc < 8; cc++)
                    o[rr][cc] = fmaf(pF[rr], vF[cc], o[rr][cc]);
        }
    }

    // Final normalize + write to g_att [b*S+s, h*64+dh]
#pragma unroll
    for (int rr = 0; rr < 4; rr++) {
        float inv = 1.f / l_i[rr];
        size_t row = (size_t)b * S_LEN + qi * 64 + ty * 4 + rr;
        float* dst = g_att + row * DM + h * DHEAD + tx * 8;
        *(float4*)&dst[0] = make_float4(o[rr][0] * inv, o[rr][1] * inv,
                                        o[rr][2] * inv, o[rr][3] * inv);
        *(float4*)&dst[4] = make_float4(o[rr][4] * inv, o[rr][5] * inv,
                                        o[rr][6] * inv, o[rr][7] * inv);
    }
}

// ---------------------------------------------------------------------------
extern "C" void kernel_launch(void* const* d_in, const int* in_sizes, int n_in,
                              void* d_out, int out_size)
{
    (void)in_sizes; (void)n_in; (void)out_size;
    const float* x  = (const float*)d_in[0];
    const float* qw = (const float*)d_in[1];
    const float* kw = (const float*)d_in[2];
    const float* vw = (const float*)d_in[3];
    const float* ow = (const float*)d_in[4];
    float* out = (float*)d_out;

    // 1) QKV projections (fused over grid.z)
    dim3 gq(DM / GBN, MROWS / GBM, 3);
    sgemm_nt<<<gq, 256>>>(x, qw, kw, vw, nullptr);

    // 2) Causal flash attention
    dim3 ga(S_LEN / 64, BATCHN * NHEAD, 1);
    flash_attn<<<ga, 128>>>();

    // 3) Output projection
    dim3 go(DM / GBN, MROWS / GBM, 1);
    sgemm_nt<<<go, 256>>>(nullptr, ow, ow, ow, out);
}

// round 3
// speedup vs baseline: 1.4533x; 1.4533x over previous
#include <cuda_runtime.h>
#include <cuda_bf16.h>
#include <cstdint>
#include <math.h>

// Problem constants
#define S_LEN 2048
#define BATCHN 2
#define DM 1024
#define NHEAD 16
#define DHEAD 64
#define MROWS (BATCHN * S_LEN)   // 4096

// ---------------------------------------------------------------------------
// Scratch (device globals: allocation-free rule)
// ---------------------------------------------------------------------------
__device__ float g_qkv[(size_t)3 * MROWS * DM];   // Q, K, V fp32
__device__ float g_att[(size_t)MROWS * DM];       // attention output fp32
__device__ __nv_bfloat16 g_xhi[(size_t)MROWS * DM];
__device__ __nv_bfloat16 g_xlo[(size_t)MROWS * DM];
__device__ __nv_bfloat16 g_whi[(size_t)4 * DM * DM];   // q,k,v,o weights split
__device__ __nv_bfloat16 g_wlo[(size_t)4 * DM * DM];
__device__ __nv_bfloat16 g_ahi[(size_t)MROWS * DM];    // attention out split
__device__ __nv_bfloat16 g_alo[(size_t)MROWS * DM];

// ---------------------------------------------------------------------------
// PTX helpers — ONLY sm_80+ features (harness targets plain compute_103:
// tcgen05/TMEM PTX is rejected by ptxas, so we use ldmatrix + mma.sync).
// ---------------------------------------------------------------------------
__device__ __forceinline__ uint32_t smem_u32(const void* p) {
    uint32_t a;
    asm("{ .reg .u64 t; cvta.to.shared.u64 t, %1; cvt.u32.u64 %0, t; }" : "=r"(a) : "l"(p));
    return a;
}

#define LDSM_X4(r0, r1, r2, r3, addr) \
    asm volatile("ldmatrix.sync.aligned.m8n8.x4.shared.b16 {%0,%1,%2,%3}, [%4];" \
                 : "=r"(r0), "=r"(r1), "=r"(r2), "=r"(r3) : "r"(addr))

#define MMA_BF16(c, a, b0, b1) \
    asm volatile("mma.sync.aligned.m16n8k16.row.col.f32.bf16.bf16.f32 " \
                 "{%0,%1,%2,%3}, {%4,%5,%6,%7}, {%8,%9}, {%0,%1,%2,%3};" \
                 : "+f"((c)[0]), "+f"((c)[1]), "+f"((c)[2]), "+f"((c)[3]) \
                 : "r"((a)[0]), "r"((a)[1]), "r"((a)[2]), "r"((a)[3]), "r"(b0), "r"(b1))

#define CP_ASYNC16(saddr, gaddr) \
    asm volatile("cp.async.cg.shared.global [%0], [%1], 16;" :: "r"(saddr), "l"(gaddr))
#define CP_COMMIT() asm volatile("cp.async.commit_group;" ::: "memory")
#define CP_WAIT1()  asm volatile("cp.async.wait_group 1;" ::: "memory")

// ---------------------------------------------------------------------------
// fp32 -> (bf16 hi, bf16 lo) split
// ---------------------------------------------------------------------------
__global__ void cvt_split(const float* __restrict__ src,
                          __nv_bfloat16* __restrict__ hi,
                          __nv_bfloat16* __restrict__ lo, int n4)
{
    int i = blockIdx.x * blockDim.x + threadIdx.x;
    if (i >= n4) return;
    float4 v = ((const float4*)src)[i];
    float x[4] = {v.x, v.y, v.z, v.w};
    __nv_bfloat16 h[4], l[4];
#pragma unroll
    for (int j = 0; j < 4; j++) {
        h[j] = __float2bfloat16(x[j]);
        l[j] = __float2bfloat16(x[j] - __bfloat162float(h[j]));
    }
    ((__nv_bfloat162*)hi)[2 * i + 0] = __nv_bfloat162(h[0], h[1]);
    ((__nv_bfloat162*)hi)[2 * i + 1] = __nv_bfloat162(h[2], h[3]);
    ((__nv_bfloat162*)lo)[2 * i + 0] = __nv_bfloat162(l[0], l[1]);
    ((__nv_bfloat162*)lo)[2 * i + 1] = __nv_bfloat162(l[2], l[3]);
}

// ---------------------------------------------------------------------------
// mma.sync split-bf16 NT GEMM: C[m,n] = sum_k A[m,k] * W[n,k]
// CTA tile 128x128, BK=32 (bf16), 8 warps (warp tile 32x64).
// 2-stage cp.async pipeline. Smem tiles use XOR-16B swizzle: a tile row is
// 64B (32 bf16); offset(row, c16) = row*64 + (c16 ^ ((row>>1)&3))*16.
// C += Ah*Wh + Ah*Wl + Al*Wh   (fp32 accumulate in registers)
// grid: (DM/128, MROWS/128, nz); W/C offset by z via strides.
// ---------------------------------------------------------------------------
#define BK 32
#define TILE_B (128 * BK * 2)          // 8192 bytes per bf16 tile
#define STAGE_B (4 * TILE_B)           // Ah|Al|Bh|Bl = 32768
#define GEMM_SMEM (2 * STAGE_B)        // 65536
#define NCHUNK (DM / BK)               // 32

__device__ __forceinline__ uint32_t sw_off(int row, int c16) {
    return (uint32_t)(row * 64 + ((c16 ^ ((row >> 1) & 3)) << 4));
}

__global__ void __launch_bounds__(256)
gemm_mma(const __nv_bfloat16* __restrict__ Ahi, const __nv_bfloat16* __restrict__ Alo,
         const __nv_bfloat16* __restrict__ Whi, const __nv_bfloat16* __restrict__ Wlo,
         float* __restrict__ Cb, long wstride, long cstride)
{
    extern __shared__ __align__(16) char smem[];
    const uint32_t sb = smem_u32(smem);
    const int tid = threadIdx.x;
    const int wid = tid >> 5, lane = tid & 31;
    const int z = blockIdx.z;
    const __nv_bfloat16* whi = Whi + (size_t)z * wstride;
    const __nv_bfloat16* wlo = Wlo + (size_t)z * wstride;
    float* C = Cb + (size_t)z * cstride;
    const int m0 = blockIdx.y * 128;
    const int n0 = blockIdx.x * 128;

    const int wm = wid & 3;            // 0..3 : 32-row slice
    const int wn = wid >> 2;           // 0..1 : 64-col slice

    float acc[2][8][4];
#pragma unroll
    for (int i = 0; i < 2; i++)
#pragma unroll
        for (int j = 0; j < 8; j++)
#pragma unroll
            for (int k = 0; k < 4; k++) acc[i][j][k] = 0.f;

    // per-thread load mapping: q in {tid, tid+256}: row=q>>2, c16=q&3
    const int r0q = tid >> 2, c0q = tid & 3;
    const int r1q = (tid + 256) >> 2, c1q = tid & 3;  // (+256 keeps c16, row+64)

    // issue loads for chunk c into stage s
    auto load_chunk = [&](int s, int c) {
        const uint32_t st = sb + s * STAGE_B;
        const int k0 = c * BK;
        {
            uint32_t o = sw_off(r0q, c0q);
            size_t ga = (size_t)(m0 + r0q) * DM + k0 + c0q * 8;
            size_t gb = (size_t)(n0 + r0q) * DM + k0 + c0q * 8;
            CP_ASYNC16(st + 0 * TILE_B + o, Ahi + ga);
            CP_ASYNC16(st + 1 * TILE_B + o, Alo + ga);
            CP_ASYNC16(st + 2 * TILE_B + o, whi + gb);
            CP_ASYNC16(st + 3 * TILE_B + o, wlo + gb);
        }
        {
            uint32_t o = sw_off(r1q, c1q);
            size_t ga = (size_t)(m0 + r1q) * DM + k0 + c1q * 8;
            size_t gb = (size_t)(n0 + r1q) * DM + k0 + c1q * 8;
            CP_ASYNC16(st + 0 * TILE_B + o, Ahi + ga);
            CP_ASYNC16(st + 1 * TILE_B + o, Alo + ga);
            CP_ASYNC16(st + 2 * TILE_B + o, whi + gb);
            CP_ASYNC16(st + 3 * TILE_B + o, wlo + gb);
        }
    };

    load_chunk(0, 0); CP_COMMIT();
    load_chunk(1, 1); CP_COMMIT();

    for (int c = 0; c < NCHUNK; c++) {
        const int buf = c & 1;
        CP_WAIT1();
        __syncthreads();

        const uint32_t st = sb + buf * STAGE_B;
        const uint32_t sAh = st + 0 * TILE_B, sAl = st + 1 * TILE_B;
        const uint32_t sBh = st + 2 * TILE_B, sBl = st + 3 * TILE_B;

#pragma unroll
        for (int ks = 0; ks < 2; ks++) {
            // A fragments: rows wm*32 + mf*16 + lane%16, chunk ks*2 + lane/16
            uint32_t ah[2][4], al[2][4];
#pragma unroll
            for (int mf = 0; mf < 2; mf++) {
                int ra = wm * 32 + mf * 16 + (lane & 15);
                int ca = ks * 2 + (lane >> 4);
                uint32_t o = sw_off(ra, ca);
                LDSM_X4(ah[mf][0], ah[mf][1], ah[mf][2], ah[mf][3], sAh + o);
                LDSM_X4(al[mf][0], al[mf][1], al[mf][2], al[mf][3], sAl + o);
            }
#pragma unroll
            for (int nfp = 0; nfp < 4; nfp++) {
                // B x4: two n-frags. rows wn*64 + nfp*16 + ((lane>>4)&1)*8 + lane%8
                int rb = wn * 64 + nfp * 16 + ((lane >> 4) & 1) * 8 + (lane & 7);
                int cbk = ks * 2 + ((lane >> 3) & 1);
                uint32_t o = sw_off(rb, cbk);
                uint32_t bh[4], bl[4];
                LDSM_X4(bh[0], bh[1], bh[2], bh[3], sBh + o);
                LDSM_X4(bl[0], bl[1], bl[2], bl[3], sBl + o);
#pragma unroll
                for (int sub = 0; sub < 2; sub++) {
                    int nf = nfp * 2 + sub;
                    uint32_t h0 = bh[sub * 2], h1 = bh[sub * 2 + 1];
                    uint32_t l0 = bl[sub * 2], l1 = bl[sub * 2 + 1];
#pragma unroll
                    for (int mf = 0; mf < 2; mf++) {
                        MMA_BF16(acc[mf][nf], ah[mf], h0, h1);
                        MMA_BF16(acc[mf][nf], ah[mf], l0, l1);
                        MMA_BF16(acc[mf][nf], al[mf], h0, h1);
                    }
                }
            }
        }
        __syncthreads();
        if (c + 2 < NCHUNK) load_chunk(buf, c + 2);
        CP_COMMIT();
    }

    // epilogue: thread (g = lane/4, t = lane%4)
    const int g = lane >> 2, t = lane & 3;
#pragma unroll
    for (int mf = 0; mf < 2; mf++) {
#pragma unroll
        for (int nf = 0; nf < 8; nf++) {
            int row = m0 + wm * 32 + mf * 16 + g;
            int col = n0 + wn * 64 + nf * 8 + 2 * t;
            float* p0 = C + (size_t)row * DM + col;
            float* p1 = C + (size_t)(row + 8) * DM + col;
            p0[0] = acc[mf][nf][0]; p0[1] = acc[mf][nf][1];
            p1[0] = acc[mf][nf][2]; p1[1] = acc[mf][nf][3];
        }
    }
}

// ---------------------------------------------------------------------------
// Causal flash attention, fp32 (unchanged from round 1 — passing)
// ---------------------------------------------------------------------------
__global__ void __launch_bounds__(128, 4)
flash_attn(void)
{
    __shared__ float sQt[DHEAD * 64];
    __shared__ float sKt[DHEAD * 64];
    __shared__ float sV [64 * DHEAD];

    const int qi = (gridDim.x - 1) - blockIdx.x;
    const int bh = blockIdx.y;
    const int b  = bh >> 4;
    const int h  = bh & 15;

    const size_t MN = (size_t)MROWS * DM;
    const float* Q  = g_qkv +          (size_t)b * S_LEN * DM + h * DHEAD;
    const float* Kp = g_qkv + MN     + (size_t)b * S_LEN * DM + h * DHEAD;
    const float* Vp = g_qkv + 2 * MN + (size_t)b * S_LEN * DM + h * DHEAD;

    const int tid = threadIdx.x;
    const int ty = tid >> 3;
    const int tx = tid & 7;

#pragma unroll
    for (int i = 0; i < 8; i++) {
        int p = tid + i * 128;
        int r = p >> 4;
        int d = (p & 15) * 4;
        float4 v = *(const float4*)(Q + (size_t)(qi * 64 + r) * DM + d);
        sQt[(d + 0) * 64 + r] = v.x;
        sQt[(d + 1) * 64 + r] = v.y;
        sQt[(d + 2) * 64 + r] = v.z;
        sQt[(d + 3) * 64 + r] = v.w;
    }

    float m_i[4], l_i[4], o[4][8];
#pragma unroll
    for (int rr = 0; rr < 4; rr++) {
        m_i[rr] = -1e30f;
        l_i[rr] = 0.f;
#pragma unroll
        for (int cc = 0; cc < 8; cc++) o[rr][cc] = 0.f;
    }

    for (int j = 0; j <= qi; j++) {
        __syncthreads();
#pragma unroll
        for (int i = 0; i < 8; i++) {
            int p = tid + i * 128;
            int r = p >> 4;
            int d = (p & 15) * 4;
            float4 kv = *(const float4*)(Kp + (size_t)(j * 64 + r) * DM + d);
            sKt[(d + 0) * 64 + r] = kv.x;
            sKt[(d + 1) * 64 + r] = kv.y;
            sKt[(d + 2) * 64 + r] = kv.z;
            sKt[(d + 3) * 64 + r] = kv.w;
            float4 vv = *(const float4*)(Vp + (size_t)(j * 64 + r) * DM + d);
            *(float4*)&sV[r * 64 + d] = vv;
        }
        __syncthreads();

        float s[4][8];
#pragma unroll
        for (int rr = 0; rr < 4; rr++)
#pragma unroll
            for (int cc = 0; cc < 8; cc++) s[rr][cc] = 0.f;

#pragma unroll 8
        for (int d = 0; d < DHEAD; d++) {
            float aF[4], bF[8];
            *(float4*)&aF[0] = *(const float4*)&sQt[d * 64 + ty * 4];
            *(float4*)&bF[0] = *(const float4*)&sKt[d * 64 + tx * 8];
            *(float4*)&bF[4] = *(const float4*)&sKt[d * 64 + tx * 8 + 4];
#pragma unroll
            for (int rr = 0; rr < 4; rr++)
#pragma unroll
                for (int cc = 0; cc < 8; cc++)
                    s[rr][cc] = fmaf(aF[rr], bF[cc], s[rr][cc]);
        }

        const float scale = 0.125f;
        if (j == qi) {
#pragma unroll
            for (int rr = 0; rr < 4; rr++)
#pragma unroll
                for (int cc = 0; cc < 8; cc++) {
                    int r = ty * 4 + rr, c = tx * 8 + cc;
                    s[rr][cc] = (c <= r) ? s[rr][cc] * scale : -1e30f;
                }
        } else {
#pragma unroll
            for (int rr = 0; rr < 4; rr++)
#pragma unroll
                for (int cc = 0; cc < 8; cc++) s[rr][cc] *= scale;
        }

        float p[4][8], corr[4], rsum[4];
#pragma unroll
        for (int rr = 0; rr < 4; rr++) {
            float tm = s[rr][0];
#pragma unroll
            for (int cc = 1; cc < 8; cc++) tm = fmaxf(tm, s[rr][cc]);
#pragma unroll
            for (int msk = 1; msk < 8; msk <<= 1)
                tm = fmaxf(tm, __shfl_xor_sync(0xffffffffu, tm, msk));
            float mnew = fmaxf(m_i[rr], tm);
            corr[rr] = __expf(m_i[rr] - mnew);
            m_i[rr] = mnew;
            float ls = 0.f;
#pragma unroll
            for (int cc = 0; cc < 8; cc++) {
                p[rr][cc] = __expf(s[rr][cc] - mnew);
                ls += p[rr][cc];
            }
#pragma unroll
            for (int msk = 1; msk < 8; msk <<= 1)
                ls += __shfl_xor_sync(0xffffffffu, ls, msk);
            rsum[rr] = ls;
        }

        __syncthreads();

#pragma unroll
        for (int rr = 0; rr < 4; rr++) {
            l_i[rr] = l_i[rr] * corr[rr] + rsum[rr];
#pragma unroll
            for (int cc = 0; cc < 8; cc++) {
                o[rr][cc] *= corr[rr];
                sKt[(tx * 8 + cc) * 64 + (ty * 4 + rr)] = p[rr][cc];
            }
        }
        __syncthreads();

#pragma unroll 8
        for (int n = 0; n < 64; n++) {
            float pF[4], vF[8];
            *(float4*)&pF[0] = *(const float4*)&sKt[n * 64 + ty * 4];
            *(float4*)&vF[0] = *(const float4*)&sV[n * 64 + tx * 8];
            *(float4*)&vF[4] = *(const float4*)&sV[n * 64 + tx * 8 + 4];
#pragma unroll
            for (int rr = 0; rr < 4; rr++)
#pragma unroll
                for (int cc = 0; cc < 8; cc++)
                    o[rr][cc] = fmaf(pF[rr], vF[cc], o[rr][cc]);
        }
    }

#pragma unroll
    for (int rr = 0; rr < 4; rr++) {
        float inv = 1.f / l_i[rr];
        size_t row = (size_t)b * S_LEN + qi * 64 + ty * 4 + rr;
        float* dst = g_att + row * DM + h * DHEAD + tx * 8;
        *(float4*)&dst[0] = make_float4(o[rr][0] * inv, o[rr][1] * inv,
                                        o[rr][2] * inv, o[rr][3] * inv);
        *(float4*)&dst[4] = make_float4(o[rr][4] * inv, o[rr][5] * inv,
                                        o[rr][6] * inv, o[rr][7] * inv);
    }
}

// ---------------------------------------------------------------------------
extern "C" void kernel_launch(void* const* d_in, const int* in_sizes, int n_in,
                              void* d_out, int out_size)
{
    (void)in_sizes; (void)n_in; (void)out_size;
    const float* x  = (const float*)d_in[0];
    const float* qw = (const float*)d_in[1];
    const float* kw = (const float*)d_in[2];
    const float* vw = (const float*)d_in[3];
    const float* ow = (const float*)d_in[4];
    float* out = (float*)d_out;

    static int cfg_done = 0;
    if (!cfg_done) {
        cudaFuncSetAttribute(gemm_mma, cudaFuncAttributeMaxDynamicSharedMemorySize, GEMM_SMEM);
        cfg_done = 1;
    }

    __nv_bfloat16 *xhi, *xlo, *whi, *wlo, *ahi, *alo;
    cudaGetSymbolAddress((void**)&xhi, g_xhi);
    cudaGetSymbolAddress((void**)&xlo, g_xlo);
    cudaGetSymbolAddress((void**)&whi, g_whi);
    cudaGetSymbolAddress((void**)&wlo, g_wlo);
    cudaGetSymbolAddress((void**)&ahi, g_ahi);
    cudaGetSymbolAddress((void**)&alo, g_alo);
    float *qkv, *att;
    cudaGetSymbolAddress((void**)&qkv, g_qkv);
    cudaGetSymbolAddress((void**)&att, g_att);

    const int nx4 = MROWS * DM / 4;
    const int nw4 = DM * DM / 4;

    // 1) split-convert inputs + weights
    cvt_split<<<(nx4 + 255) / 256, 256>>>(x, xhi, xlo, nx4);
    cvt_split<<<(nw4 + 255) / 256, 256>>>(qw, whi + 0ul * DM * DM, wlo + 0ul * DM * DM, nw4);
    cvt_split<<<(nw4 + 255) / 256, 256>>>(kw, whi + 1ul * DM * DM, wlo + 1ul * DM * DM, nw4);
    cvt_split<<<(nw4 + 255) / 256, 256>>>(vw, whi + 2ul * DM * DM, wlo + 2ul * DM * DM, nw4);
    cvt_split<<<(nw4 + 255) / 256, 256>>>(ow, whi + 3ul * DM * DM, wlo + 3ul * DM * DM, nw4);

    // 2) QKV projection (tensor cores via mma.sync; z selects weight/output)
    dim3 gq(DM / 128, MROWS / 128, 3);
    gemm_mma<<<gq, 256, GEMM_SMEM>>>(xhi, xlo, whi, wlo, qkv,
                                     (long)DM * DM, (long)MROWS * DM);

    // 3) Causal flash attention (fp32)
    dim3 ga(S_LEN / 64, BATCHN * NHEAD, 1);
    flash_attn<<<ga, 128>>>();

    // 4) split-convert attention output, then O projection
    cvt_split<<<(nx4 + 255) / 256, 256>>>(att, ahi, alo, nx4);
    dim3 go(DM / 128, MROWS / 128, 1);
    gemm_mma<<<go, 256, GEMM_SMEM>>>(ahi, alo, whi + 3ul * DM * DM, wlo + 3ul * DM * DM,
                                     out, 0L, 0L);
}

// round 5
// speedup vs baseline: 3.9606x; 2.7252x over previous
#include <cuda_runtime.h>
#include <cuda_bf16.h>
#include <cstdint>
#include <math.h>

// Problem constants
#define S_LEN 2048
#define BATCHN 2
#define DM 1024
#define NHEAD 16
#define DHEAD 64
#define MROWS (BATCHN * S_LEN)   // 4096

// ---------------------------------------------------------------------------
// Scratch (device globals: allocation-free rule)
// ---------------------------------------------------------------------------
__device__ __nv_bfloat16 g_qkvh[(size_t)3 * MROWS * DM];  // Q|K|V hi
__device__ __nv_bfloat16 g_qkvl[(size_t)3 * MROWS * DM];  // Q|K|V lo
__device__ __nv_bfloat16 g_xhi[(size_t)MROWS * DM];
__device__ __nv_bfloat16 g_xlo[(size_t)MROWS * DM];
__device__ __nv_bfloat16 g_whi[(size_t)4 * DM * DM];      // q,k,v,o weights split
__device__ __nv_bfloat16 g_wlo[(size_t)4 * DM * DM];
__device__ __nv_bfloat16 g_ahi[(size_t)MROWS * DM];       // attention out split
__device__ __nv_bfloat16 g_alo[(size_t)MROWS * DM];

// ---------------------------------------------------------------------------
// PTX helpers — sm_80+ only (plain compute_103 target: no tcgen05)
// ---------------------------------------------------------------------------
__device__ __forceinline__ uint32_t smem_u32(const void* p) {
    uint32_t a;
    asm("{ .reg .u64 t; cvta.to.shared.u64 t, %1; cvt.u32.u64 %0, t; }" : "=r"(a) : "l"(p));
    return a;
}

#define LDSM_X4(r0, r1, r2, r3, addr) \
    asm volatile("ldmatrix.sync.aligned.m8n8.x4.shared.b16 {%0,%1,%2,%3}, [%4];" \
                 : "=r"(r0), "=r"(r1), "=r"(r2), "=r"(r3) : "r"(addr))

#define LDSM_X4_T(r0, r1, r2, r3, addr) \
    asm volatile("ldmatrix.sync.aligned.m8n8.x4.trans.shared.b16 {%0,%1,%2,%3}, [%4];" \
                 : "=r"(r0), "=r"(r1), "=r"(r2), "=r"(r3) : "r"(addr))

#define MMA_BF16(c, a, b0, b1) \
    asm volatile("mma.sync.aligned.m16n8k16.row.col.f32.bf16.bf16.f32 " \
                 "{%0,%1,%2,%3}, {%4,%5,%6,%7}, {%8,%9}, {%0,%1,%2,%3};" \
                 : "+f"((c)[0]), "+f"((c)[1]), "+f"((c)[2]), "+f"((c)[3]) \
                 : "r"((a)[0]), "r"((a)[1]), "r"((a)[2]), "r"((a)[3]), "r"(b0), "r"(b1))

#define CP_ASYNC16(saddr, gaddr) \
    asm volatile("cp.async.cg.shared.global [%0], [%1], 16;" :: "r"(saddr), "l"(gaddr))
#define CP_COMMIT() asm volatile("cp.async.commit_group;" ::: "memory")
#define CP_WAIT0()  asm volatile("cp.async.wait_group 0;" ::: "memory")
#define CP_WAIT1()  asm volatile("cp.async.wait_group 1;" ::: "memory")

// split two fp32 into bf16 hi-pair + lo-pair (packed b16x2)
__device__ __forceinline__ void split2(float x, float y, uint32_t& hi, uint32_t& lo) {
    __nv_bfloat162 h = __floats2bfloat162_rn(x, y);
    __nv_bfloat162 l = __floats2bfloat162_rn(x - __bfloat162float(h.x),
                                             y - __bfloat162float(h.y));
    hi = *(uint32_t*)&h;
    lo = *(uint32_t*)&l;
}

// ---------------------------------------------------------------------------
// fp32 -> (bf16 hi, bf16 lo) split
// ---------------------------------------------------------------------------
__global__ void cvt_split(const float* __restrict__ src,
                          __nv_bfloat16* __restrict__ hi,
                          __nv_bfloat16* __restrict__ lo, int n4)
{
    int i = blockIdx.x * blockDim.x + threadIdx.x;
    if (i >= n4) return;
    float4 v = ((const float4*)src)[i];
    float x[4] = {v.x, v.y, v.z, v.w};
    __nv_bfloat16 h[4], l[4];
#pragma unroll
    for (int j = 0; j < 4; j++) {
        h[j] = __float2bfloat16(x[j]);
        l[j] = __float2bfloat16(x[j] - __bfloat162float(h[j]));
    }
    ((__nv_bfloat162*)hi)[2 * i + 0] = __nv_bfloat162(h[0], h[1]);
    ((__nv_bfloat162*)hi)[2 * i + 1] = __nv_bfloat162(h[2], h[3]);
    ((__nv_bfloat162*)lo)[2 * i + 0] = __nv_bfloat162(l[0], l[1]);
    ((__nv_bfloat162*)lo)[2 * i + 1] = __nv_bfloat162(l[2], l[3]);
}

// ---------------------------------------------------------------------------
// mma.sync split-bf16 NT GEMM (same core as round 3, passing).
// Output either fp32 (Cf) or split hi/lo bf16 (Chi/Clo).
// ---------------------------------------------------------------------------
#define BK 32
#define TILE_B (128 * BK * 2)
#define STAGE_B (4 * TILE_B)
#define GEMM_SMEM (2 * STAGE_B)
#define NCHUNK (DM / BK)

__device__ __forceinline__ uint32_t sw_off(int row, int c16) {
    return (uint32_t)(row * 64 + ((c16 ^ ((row >> 1) & 3)) << 4));
}

__global__ void __launch_bounds__(256)
gemm_mma(const __nv_bfloat16* __restrict__ Ahi, const __nv_bfloat16* __restrict__ Alo,
         const __nv_bfloat16* __restrict__ Whi, const __nv_bfloat16* __restrict__ Wlo,
         float* __restrict__ Cf, __nv_bfloat16* __restrict__ Chi,
         __nv_bfloat16* __restrict__ Clo, long wstride, long cstride)
{
    extern __shared__ __align__(16) char smem[];
    const uint32_t sb = smem_u32(smem);
    const int tid = threadIdx.x;
    const int wid = tid >> 5, lane = tid & 31;
    const int z = blockIdx.z;
    const __nv_bfloat16* whi = Whi + (size_t)z * wstride;
    const __nv_bfloat16* wlo = Wlo + (size_t)z * wstride;
    const int m0 = blockIdx.y * 128;
    const int n0 = blockIdx.x * 128;

    const int wm = wid & 3;
    const int wn = wid >> 2;

    float acc[2][8][4];
#pragma unroll
    for (int i = 0; i < 2; i++)
#pragma unroll
        for (int j = 0; j < 8; j++)
#pragma unroll
            for (int k = 0; k < 4; k++) acc[i][j][k] = 0.f;

    const int r0q = tid >> 2, c0q = tid & 3;
    const int r1q = (tid + 256) >> 2, c1q = tid & 3;

    auto load_chunk = [&](int s, int c) {
        const uint32_t st = sb + s * STAGE_B;
        const int k0 = c * BK;
        {
            uint32_t o = sw_off(r0q, c0q);
            size_t ga = (size_t)(m0 + r0q) * DM + k0 + c0q * 8;
            size_t gb = (size_t)(n0 + r0q) * DM + k0 + c0q * 8;
            CP_ASYNC16(st + 0 * TILE_B + o, Ahi + ga);
            CP_ASYNC16(st + 1 * TILE_B + o, Alo + ga);
            CP_ASYNC16(st + 2 * TILE_B + o, whi + gb);
            CP_ASYNC16(st + 3 * TILE_B + o, wlo + gb);
        }
        {
            uint32_t o = sw_off(r1q, c1q);
            size_t ga = (size_t)(m0 + r1q) * DM + k0 + c1q * 8;
            size_t gb = (size_t)(n0 + r1q) * DM + k0 + c1q * 8;
            CP_ASYNC16(st + 0 * TILE_B + o, Ahi + ga);
            CP_ASYNC16(st + 1 * TILE_B + o, Alo + ga);
            CP_ASYNC16(st + 2 * TILE_B + o, whi + gb);
            CP_ASYNC16(st + 3 * TILE_B + o, wlo + gb);
        }
    };

    load_chunk(0, 0); CP_COMMIT();
    load_chunk(1, 1); CP_COMMIT();

    for (int c = 0; c < NCHUNK; c++) {
        const int buf = c & 1;
        CP_WAIT1();
        __syncthreads();

        const uint32_t st = sb + buf * STAGE_B;
        const uint32_t sAh = st + 0 * TILE_B, sAl = st + 1 * TILE_B;
        const uint32_t sBh = st + 2 * TILE_B, sBl = st + 3 * TILE_B;

#pragma unroll
        for (int ks = 0; ks < 2; ks++) {
            uint32_t ah[2][4], al[2][4];
#pragma unroll
            for (int mf = 0; mf < 2; mf++) {
                int ra = wm * 32 + mf * 16 + (lane & 15);
                int ca = ks * 2 + (lane >> 4);
                uint32_t o = sw_off(ra, ca);
                LDSM_X4(ah[mf][0], ah[mf][1], ah[mf][2], ah[mf][3], sAh + o);
                LDSM_X4(al[mf][0], al[mf][1], al[mf][2], al[mf][3], sAl + o);
            }
#pragma unroll
            for (int nfp = 0; nfp < 4; nfp++) {
                int rb = wn * 64 + nfp * 16 + ((lane >> 4) & 1) * 8 + (lane & 7);
                int cbk = ks * 2 + ((lane >> 3) & 1);
                uint32_t o = sw_off(rb, cbk);
                uint32_t bh[4], bl[4];
                LDSM_X4(bh[0], bh[1], bh[2], bh[3], sBh + o);
                LDSM_X4(bl[0], bl[1], bl[2], bl[3], sBl + o);
#pragma unroll
                for (int sub = 0; sub < 2; sub++) {
                    int nf = nfp * 2 + sub;
                    uint32_t h0 = bh[sub * 2], h1 = bh[sub * 2 + 1];
                    uint32_t l0 = bl[sub * 2], l1 = bl[sub * 2 + 1];
#pragma unroll
                    for (int mf = 0; mf < 2; mf++) {
                        MMA_BF16(acc[mf][nf], ah[mf], h0, h1);
                        MMA_BF16(acc[mf][nf], ah[mf], l0, l1);
                        MMA_BF16(acc[mf][nf], al[mf], h0, h1);
                    }
                }
            }
        }
        __syncthreads();
        if (c + 2 < NCHUNK) load_chunk(buf, c + 2);
        CP_COMMIT();
    }

    const int g = lane >> 2, t = lane & 3;
    if (Cf) {
        float* C = Cf + (size_t)z * cstride;
#pragma unroll
        for (int mf = 0; mf < 2; mf++)
#pragma unroll
            for (int nf = 0; nf < 8; nf++) {
                int row = m0 + wm * 32 + mf * 16 + g;
                int col = n0 + wn * 64 + nf * 8 + 2 * t;
                float* p0 = C + (size_t)row * DM + col;
                float* p1 = C + (size_t)(row + 8) * DM + col;
                p0[0] = acc[mf][nf][0]; p0[1] = acc[mf][nf][1];
                p1[0] = acc[mf][nf][2]; p1[1] = acc[mf][nf][3];
            }
    } else {
        __nv_bfloat16* CH = Chi + (size_t)z * cstride;
        __nv_bfloat16* CL = Clo + (size_t)z * cstride;
#pragma unroll
        for (int mf = 0; mf < 2; mf++)
#pragma unroll
            for (int nf = 0; nf < 8; nf++) {
                int row = m0 + wm * 32 + mf * 16 + g;
                int col = n0 + wn * 64 + nf * 8 + 2 * t;
                uint32_t h0, l0, h1, l1;
                split2(acc[mf][nf][0], acc[mf][nf][1], h0, l0);
                split2(acc[mf][nf][2], acc[mf][nf][3], h1, l1);
                *(uint32_t*)(CH + (size_t)row * DM + col) = h0;
                *(uint32_t*)(CL + (size_t)row * DM + col) = l0;
                *(uint32_t*)(CH + (size_t)(row + 8) * DM + col) = h1;
                *(uint32_t*)(CL + (size_t)(row + 8) * DM + col) = l1;
            }
    }
}

// ---------------------------------------------------------------------------
// Tensor-core causal flash attention, split-bf16 (3-product) QK^T and P.V.
// Block = 4 warps, Q tile 64 rows (16/warp), KV tile 64, dh = 64.
// Smem: Qh|Ql (8KB ea) + 2-stage {Kh,Kl,Vh,Vl} (8KB ea) = 80KB dynamic.
// Swizzle: 128B rows, FSW(row,c16) = row*128 + ((c16 ^ (row&7))<<4).
// ---------------------------------------------------------------------------
#define FSW(row, c16) ((uint32_t)((row) * 128 + ((((c16) ^ ((row) & 7))) << 4)))
#define FA_SMEM (16384 + 2 * 32768)   // 81920

__global__ void __launch_bounds__(128)
flash_mma(void)
{
    extern __shared__ __align__(16) char fsm[];
    const uint32_t sb = smem_u32(fsm);
    const uint32_t sQh = sb, sQl = sb + 8192;

    const int qi = (gridDim.x - 1) - blockIdx.x;   // big tiles first
    const int b  = blockIdx.y >> 4;
    const int h  = blockIdx.y & 15;

    const int tid = threadIdx.x;
    const int w = tid >> 5, lane = tid & 31;

    const size_t MN = (size_t)MROWS * DM;
    const size_t base = (size_t)b * S_LEN * DM + h * DHEAD;
    const __nv_bfloat16* Qh = g_qkvh + base;
    const __nv_bfloat16* Ql = g_qkvl + base;
    const __nv_bfloat16* Kh = g_qkvh + MN + base;
    const __nv_bfloat16* Kl = g_qkvl + MN + base;
    const __nv_bfloat16* Vh = g_qkvh + 2 * MN + base;
    const __nv_bfloat16* Vl = g_qkvl + 2 * MN + base;

    auto load_kv = [&](int stage, int j) {
        const uint32_t st = sb + 16384 + stage * 32768;
#pragma unroll
        for (int i = 0; i < 4; i++) {
            int idx = tid + i * 128;
            int row = idx >> 3, c16 = idx & 7;
            uint32_t o = FSW(row, c16);
            size_t gmo = (size_t)(j * 64 + row) * DM + c16 * 8;
            CP_ASYNC16(st + 0     + o, Kh + gmo);
            CP_ASYNC16(st + 8192  + o, Kl + gmo);
            CP_ASYNC16(st + 16384 + o, Vh + gmo);
            CP_ASYNC16(st + 24576 + o, Vl + gmo);
        }
    };

    // prologue: Q tile + KV stage 0, one commit group
#pragma unroll
    for (int i = 0; i < 4; i++) {
        int idx = tid + i * 128;
        int row = idx >> 3, c16 = idx & 7;
        uint32_t o = FSW(row, c16);
        size_t gmo = (size_t)(qi * 64 + row) * DM + c16 * 8;
        CP_ASYNC16(sQh + o, Qh + gmo);
        CP_ASYNC16(sQl + o, Ql + gmo);
    }
    load_kv(0, 0);
    CP_COMMIT();

    float o_acc[8][4];
#pragma unroll
    for (int i = 0; i < 8; i++)
#pragma unroll
        for (int k = 0; k < 4; k++) o_acc[i][k] = 0.f;
    float m0 = -1e30f, m1 = -1e30f, l0 = 0.f, l1 = 0.f;

    for (int j = 0; j <= qi; j++) {
        const int buf = j & 1;
        __syncthreads();                    // all warps done with stage buf
        if (j < qi) { load_kv(buf ^ 1, j + 1); CP_COMMIT(); }
        if (j < qi) { CP_WAIT1(); } else { CP_WAIT0(); }
        __syncthreads();

        const uint32_t st  = sb + 16384 + buf * 32768;
        const uint32_t stKh = st, stKl = st + 8192;
        const uint32_t stVh = st + 16384, stVl = st + 24576;

        // ---- S = Q K^T (split-bf16, 3 products) ----
        float s[8][4];
#pragma unroll
        for (int i = 0; i < 8; i++)
#pragma unroll
            for (int k = 0; k < 4; k++) s[i][k] = 0.f;

#pragma unroll
        for (int ks = 0; ks < 4; ks++) {
            uint32_t ah[4], al[4];
            uint32_t oA = FSW(w * 16 + (lane & 15), ks * 2 + (lane >> 4));
            LDSM_X4(ah[0], ah[1], ah[2], ah[3], sQh + oA);
            LDSM_X4(al[0], al[1], al[2], al[3], sQl + oA);
#pragma unroll
            for (int nfp = 0; nfp < 4; nfp++) {
                uint32_t oB = FSW(nfp * 16 + ((lane >> 4) & 1) * 8 + (lane & 7),
                                  ks * 2 + ((lane >> 3) & 1));
                uint32_t bh[4], bl[4];
                LDSM_X4(bh[0], bh[1], bh[2], bh[3], stKh + oB);
                LDSM_X4(bl[0], bl[1], bl[2], bl[3], stKl + oB);
#pragma unroll
                for (int sub = 0; sub < 2; sub++) {
                    int nf = nfp * 2 + sub;
                    MMA_BF16(s[nf], ah, bh[sub * 2], bh[sub * 2 + 1]);
                    MMA_BF16(s[nf], ah, bl[sub * 2], bl[sub * 2 + 1]);
                    MMA_BF16(s[nf], al, bh[sub * 2], bh[sub * 2 + 1]);
                }
            }
        }

        // ---- scale + causal mask ----
        const float scale = 0.125f;
        const int rg = w * 16 + (lane >> 2);     // row for c0,c1; rg+8 for c2,c3
        const int cb = (lane & 3) * 2;
        if (j == qi) {
#pragma unroll
            for (int nf = 0; nf < 8; nf++) {
                int c0 = nf * 8 + cb;
                s[nf][0] = (c0     <= rg    ) ? s[nf][0] * scale : -1e30f;
                s[nf][1] = (c0 + 1 <= rg    ) ? s[nf][1] * scale : -1e30f;
                s[nf][2] = (c0     <= rg + 8) ? s[nf][2] * scale : -1e30f;
                s[nf][3] = (c0 + 1 <= rg + 8) ? s[nf][3] * scale : -1e30f;
            }
        } else {
#pragma unroll
            for (int nf = 0; nf < 8; nf++)
#pragma unroll
                for (int k = 0; k < 4; k++) s[nf][k] *= scale;
        }

        // ---- online softmax (rows rg and rg+8; quad = lanes sharing g) ----
        float mx0 = s[0][0], mx1 = s[0][2];
#pragma unroll
        for (int nf = 0; nf < 8; nf++) {
            mx0 = fmaxf(mx0, fmaxf(s[nf][0], s[nf][1]));
            mx1 = fmaxf(mx1, fmaxf(s[nf][2], s[nf][3]));
        }
        mx0 = fmaxf(mx0, __shfl_xor_sync(0xffffffffu, mx0, 1));
        mx0 = fmaxf(mx0, __shfl_xor_sync(0xffffffffu, mx0, 2));
        mx1 = fmaxf(mx1, __shfl_xor_sync(0xffffffffu, mx1, 1));
        mx1 = fmaxf(mx1, __shfl_xor_sync(0xffffffffu, mx1, 2));

        float mn0 = fmaxf(m0, mx0), mn1 = fmaxf(m1, mx1);
        float cr0 = __expf(m0 - mn0), cr1 = __expf(m1 - mn1);
        m0 = mn0; m1 = mn1;

        float sum0 = 0.f, sum1 = 0.f;
#pragma unroll
        for (int nf = 0; nf < 8; nf++) {
            s[nf][0] = __expf(s[nf][0] - mn0); sum0 += s[nf][0];
            s[nf][1] = __expf(s[nf][1] - mn0); sum0 += s[nf][1];
            s[nf][2] = __expf(s[nf][2] - mn1); sum1 += s[nf][2];
            s[nf][3] = __expf(s[nf][3] - mn1); sum1 += s[nf][3];
        }
        sum0 += __shfl_xor_sync(0xffffffffu, sum0, 1);
        sum0 += __shfl_xor_sync(0xffffffffu, sum0, 2);
        sum1 += __shfl_xor_sync(0xffffffffu, sum1, 1);
        sum1 += __shfl_xor_sync(0xffffffffu, sum1, 2);
        l0 = l0 * cr0 + sum0;
        l1 = l1 * cr1 + sum1;

#pragma unroll
        for (int nf = 0; nf < 8; nf++) {
            o_acc[nf][0] *= cr0; o_acc[nf][1] *= cr0;
            o_acc[nf][2] *= cr1; o_acc[nf][3] *= cr1;
        }

        // ---- O += P V (split-bf16 P from registers, V via ldmatrix.trans) ----
#pragma unroll
        for (int ks = 0; ks < 4; ks++) {
            uint32_t ah[4], al[4];
            split2(s[2 * ks][0],     s[2 * ks][1],     ah[0], al[0]);
            split2(s[2 * ks][2],     s[2 * ks][3],     ah[1], al[1]);
            split2(s[2 * ks + 1][0], s[2 * ks + 1][1], ah[2], al[2]);
            split2(s[2 * ks + 1][2], s[2 * ks + 1][3], ah[3], al[3]);
#pragma unroll
            for (int nfp = 0; nfp < 4; nfp++) {
                uint32_t oV = FSW(ks * 16 + ((lane >> 3) & 1) * 8 + (lane & 7),
                                  nfp * 2 + (lane >> 4));
                uint32_t vh[4], vl[4];
                LDSM_X4_T(vh[0], vh[1], vh[2], vh[3], stVh + oV);
                LDSM_X4_T(vl[0], vl[1], vl[2], vl[3], stVl + oV);
#pragma unroll
                for (int sub = 0; sub < 2; sub++) {
                    int nf = nfp * 2 + sub;
                    MMA_BF16(o_acc[nf], ah, vh[sub * 2], vh[sub * 2 + 1]);
                    MMA_BF16(o_acc[nf], ah, vl[sub * 2], vl[sub * 2 + 1]);
                    MMA_BF16(o_acc[nf], al, vh[sub * 2], vh[sub * 2 + 1]);
                }
            }
        }
    }

    // ---- epilogue: normalize + split-write to g_ahi/g_alo ----
    const float inv0 = 1.f / l0, inv1 = 1.f / l1;
    const int rg = qi * 64 + w * 16 + (lane >> 2);
    const size_t row0 = (size_t)b * S_LEN + rg;
    const int colb = h * 64 + (lane & 3) * 2;
#pragma unroll
    for (int nf = 0; nf < 8; nf++) {
        int col = colb + nf * 8;
        uint32_t h0, l0b, h1, l1b;
        split2(o_acc[nf][0] * inv0, o_acc[nf][1] * inv0, h0, l0b);
        split2(o_acc[nf][2] * inv1, o_acc[nf][3] * inv1, h1, l1b);
        *(uint32_t*)(g_ahi + row0 * DM + col) = h0;
        *(uint32_t*)(g_alo + row0 * DM + col) = l0b;
        *(uint32_t*)(g_ahi + (row0 + 8) * DM + col) = h1;
        *(uint32_t*)(g_alo + (row0 + 8) * DM + col) = l1b;
    }
}

// ---------------------------------------------------------------------------
extern "C" void kernel_launch(void* const* d_in, const int* in_sizes, int n_in,
                              void* d_out, int out_size)
{
    (void)in_sizes; (void)n_in; (void)out_size;
    const float* x  = (const float*)d_in[0];
    const float* qw = (const float*)d_in[1];
    const float* kw = (const float*)d_in[2];
    const float* vw = (const float*)d_in[3];
    const float* ow = (const float*)d_in[4];
    float* out = (float*)d_out;

    cudaFuncSetAttribute(gemm_mma, cudaFuncAttributeMaxDynamicSharedMemorySize, GEMM_SMEM);
    cudaFuncSetAttribute(flash_mma, cudaFuncAttributeMaxDynamicSharedMemorySize, FA_SMEM);

    __nv_bfloat16 *xhi, *xlo, *whi, *wlo, *ahi, *alo, *qkvh, *qkvl;
    cudaGetSymbolAddress((void**)&xhi, g_xhi);
    cudaGetSymbolAddress((void**)&xlo, g_xlo);
    cudaGetSymbolAddress((void**)&whi, g_whi);
    cudaGetSymbolAddress((void**)&wlo, g_wlo);
    cudaGetSymbolAddress((void**)&ahi, g_ahi);
    cudaGetSymbolAddress((void**)&alo, g_alo);
    cudaGetSymbolAddress((void**)&qkvh, g_qkvh);
    cudaGetSymbolAddress((void**)&qkvl, g_qkvl);

    const int nx4 = MROWS * DM / 4;
    const int nw4 = DM * DM / 4;

    // 1) split-convert input + weights
    cvt_split<<<(nx4 + 255) / 256, 256>>>(x, xhi, xlo, nx4);
    cvt_split<<<(nw4 + 255) / 256, 256>>>(qw, whi + 0ul * DM * DM, wlo + 0ul * DM * DM, nw4);
    cvt_split<<<(nw4 + 255) / 256, 256>>>(kw, whi + 1ul * DM * DM, wlo + 1ul * DM * DM, nw4);
    cvt_split<<<(nw4 + 255) / 256, 256>>>(vw, whi + 2ul * DM * DM, wlo + 2ul * DM * DM, nw4);
    cvt_split<<<(nw4 + 255) / 256, 256>>>(ow, whi + 3ul * DM * DM, wlo + 3ul * DM * DM, nw4);

    // 2) QKV projection -> split bf16 Q|K|V directly
    dim3 gq(DM / 128, MROWS / 128, 3);
    gemm_mma<<<gq, 256, GEMM_SMEM>>>(xhi, xlo, whi, wlo,
                                     nullptr, qkvh, qkvl,
                                     (long)DM * DM, (long)MROWS * DM);

    // 3) tensor-core causal flash attention -> split bf16 att directly
    dim3 ga(S_LEN / 64, BATCHN * NHEAD, 1);
    flash_mma<<<ga, 128, FA_SMEM>>>();

    // 4) O projection -> fp32 final output
    dim3 go(DM / 128, MROWS / 128, 1);
    gemm_mma<<<go, 256, GEMM_SMEM>>>(ahi, alo, whi + 3ul * DM * DM, wlo + 3ul * DM * DM,
                                     out, nullptr, nullptr, 0L, 0L);
}

// round 6
// speedup vs baseline: 4.1460x; 1.0468x over previous
#include <cuda_runtime.h>
#include <cuda_bf16.h>
#include <cuda_fp16.h>
#include <cstdint>
#include <math.h>

// Problem constants
#define S_LEN 2048
#define BATCHN 2
#define DM 1024
#define NHEAD 16
#define DHEAD 64
#define MROWS (BATCHN * S_LEN)   // 4096

// ---------------------------------------------------------------------------
// Scratch (device globals: allocation-free rule)
// ---------------------------------------------------------------------------
__device__ __nv_bfloat16 g_qkvh[(size_t)2 * MROWS * DM];  // Q|K hi
__device__ __nv_bfloat16 g_qkvl[(size_t)2 * MROWS * DM];  // Q|K lo
__device__ __half        g_vf16[(size_t)MROWS * DM];      // V fp16 single
__device__ __nv_bfloat16 g_xhi[(size_t)MROWS * DM];
__device__ __nv_bfloat16 g_xlo[(size_t)MROWS * DM];
__device__ __nv_bfloat16 g_whi[(size_t)4 * DM * DM];      // q,k,v,o weights split
__device__ __nv_bfloat16 g_wlo[(size_t)4 * DM * DM];
__device__ __nv_bfloat16 g_ahi[(size_t)MROWS * DM];       // attention out split
__device__ __nv_bfloat16 g_alo[(size_t)MROWS * DM];

// ---------------------------------------------------------------------------
// PTX helpers — sm_80+ only (plain compute_103 target: no tcgen05)
// ---------------------------------------------------------------------------
__device__ __forceinline__ uint32_t smem_u32(const void* p) {
    uint32_t a;
    asm("{ .reg .u64 t; cvta.to.shared.u64 t, %1; cvt.u32.u64 %0, t; }" : "=r"(a) : "l"(p));
    return a;
}

#define LDSM_X4(r0, r1, r2, r3, addr) \
    asm volatile("ldmatrix.sync.aligned.m8n8.x4.shared.b16 {%0,%1,%2,%3}, [%4];" \
                 : "=r"(r0), "=r"(r1), "=r"(r2), "=r"(r3) : "r"(addr))

#define LDSM_X4_T(r0, r1, r2, r3, addr) \
    asm volatile("ldmatrix.sync.aligned.m8n8.x4.trans.shared.b16 {%0,%1,%2,%3}, [%4];" \
                 : "=r"(r0), "=r"(r1), "=r"(r2), "=r"(r3) : "r"(addr))

#define MMA_BF16(c, a, b0, b1) \
    asm volatile("mma.sync.aligned.m16n8k16.row.col.f32.bf16.bf16.f32 " \
                 "{%0,%1,%2,%3}, {%4,%5,%6,%7}, {%8,%9}, {%0,%1,%2,%3};" \
                 : "+f"((c)[0]), "+f"((c)[1]), "+f"((c)[2]), "+f"((c)[3]) \
                 : "r"((a)[0]), "r"((a)[1]), "r"((a)[2]), "r"((a)[3]), "r"(b0), "r"(b1))

#define MMA_FP16(c, a, b0, b1) \
    asm volatile("mma.sync.aligned.m16n8k16.row.col.f32.f16.f16.f32 " \
                 "{%0,%1,%2,%3}, {%4,%5,%6,%7}, {%8,%9}, {%0,%1,%2,%3};" \
                 : "+f"((c)[0]), "+f"((c)[1]), "+f"((c)[2]), "+f"((c)[3]) \
                 : "r"((a)[0]), "r"((a)[1]), "r"((a)[2]), "r"((a)[3]), "r"(b0), "r"(b1))

#define CP_ASYNC16(saddr, gaddr) \
    asm volatile("cp.async.cg.shared.global [%0], [%1], 16;" :: "r"(saddr), "l"(gaddr))
#define CP_COMMIT() asm volatile("cp.async.commit_group;" ::: "memory")
#define CP_WAIT0()  asm volatile("cp.async.wait_group 0;" ::: "memory")
#define CP_WAIT1()  asm volatile("cp.async.wait_group 1;" ::: "memory")

// split two fp32 into bf16 hi-pair + lo-pair (packed b16x2)
__device__ __forceinline__ void split2(float x, float y, uint32_t& hi, uint32_t& lo) {
    __nv_bfloat162 h = __floats2bfloat162_rn(x, y);
    __nv_bfloat162 l = __floats2bfloat162_rn(x - __bfloat162float(h.x),
                                             y - __bfloat162float(h.y));
    hi = *(uint32_t*)&h;
    lo = *(uint32_t*)&l;
}
__device__ __forceinline__ uint32_t pack_h2(float x, float y) {
    __half2 h = __floats2half2_rn(x, y);
    return *(uint32_t*)&h;
}

// ---------------------------------------------------------------------------
// fp32 -> (bf16 hi, bf16 lo) split
// ---------------------------------------------------------------------------
__global__ void cvt_split(const float* __restrict__ src,
                          __nv_bfloat16* __restrict__ hi,
                          __nv_bfloat16* __restrict__ lo, int n4)
{
    int i = blockIdx.x * blockDim.x + threadIdx.x;
    if (i >= n4) return;
    float4 v = ((const float4*)src)[i];
    float x[4] = {v.x, v.y, v.z, v.w};
    __nv_bfloat16 h[4], l[4];
#pragma unroll
    for (int j = 0; j < 4; j++) {
        h[j] = __float2bfloat16(x[j]);
        l[j] = __float2bfloat16(x[j] - __bfloat162float(h[j]));
    }
    ((__nv_bfloat162*)hi)[2 * i + 0] = __nv_bfloat162(h[0], h[1]);
    ((__nv_bfloat162*)hi)[2 * i + 1] = __nv_bfloat162(h[2], h[3]);
    ((__nv_bfloat162*)lo)[2 * i + 0] = __nv_bfloat162(l[0], l[1]);
    ((__nv_bfloat162*)lo)[2 * i + 1] = __nv_bfloat162(l[2], l[3]);
}

// ---------------------------------------------------------------------------
// mma.sync split-bf16 NT GEMM (core unchanged from passing round 5).
// Epilogue: Cf != 0 -> fp32 | z==2 && V16 -> fp16 single | else bf16 hi/lo.
// ---------------------------------------------------------------------------
#define BK 32
#define TILE_B (128 * BK * 2)
#define STAGE_B (4 * TILE_B)
#define GEMM_SMEM (2 * STAGE_B)
#define NCHUNK (DM / BK)

__device__ __forceinline__ uint32_t sw_off(int row, int c16) {
    return (uint32_t)(row * 64 + ((c16 ^ ((row >> 1) & 3)) << 4));
}

__global__ void __launch_bounds__(256)
gemm_mma(const __nv_bfloat16* __restrict__ Ahi, const __nv_bfloat16* __restrict__ Alo,
         const __nv_bfloat16* __restrict__ Whi, const __nv_bfloat16* __restrict__ Wlo,
         float* __restrict__ Cf, __nv_bfloat16* __restrict__ Chi,
         __nv_bfloat16* __restrict__ Clo, __half* __restrict__ V16,
         long wstride, long cstride)
{
    extern __shared__ __align__(16) char smem[];
    const uint32_t sb = smem_u32(smem);
    const int tid = threadIdx.x;
    const int wid = tid >> 5, lane = tid & 31;
    const int z = blockIdx.z;
    const __nv_bfloat16* whi = Whi + (size_t)z * wstride;
    const __nv_bfloat16* wlo = Wlo + (size_t)z * wstride;
    const int m0 = blockIdx.y * 128;
    const int n0 = blockIdx.x * 128;

    const int wm = wid & 3;
    const int wn = wid >> 2;

    float acc[2][8][4];
#pragma unroll
    for (int i = 0; i < 2; i++)
#pragma unroll
        for (int j = 0; j < 8; j++)
#pragma unroll
            for (int k = 0; k < 4; k++) acc[i][j][k] = 0.f;

    const int r0q = tid >> 2, c0q = tid & 3;
    const int r1q = (tid + 256) >> 2, c1q = tid & 3;

    auto load_chunk = [&](int s, int c) {
        const uint32_t st = sb + s * STAGE_B;
        const int k0 = c * BK;
        {
            uint32_t o = sw_off(r0q, c0q);
            size_t ga = (size_t)(m0 + r0q) * DM + k0 + c0q * 8;
            size_t gb = (size_t)(n0 + r0q) * DM + k0 + c0q * 8;
            CP_ASYNC16(st + 0 * TILE_B + o, Ahi + ga);
            CP_ASYNC16(st + 1 * TILE_B + o, Alo + ga);
            CP_ASYNC16(st + 2 * TILE_B + o, whi + gb);
            CP_ASYNC16(st + 3 * TILE_B + o, wlo + gb);
        }
        {
            uint32_t o = sw_off(r1q, c1q);
            size_t ga = (size_t)(m0 + r1q) * DM + k0 + c1q * 8;
            size_t gb = (size_t)(n0 + r1q) * DM + k0 + c1q * 8;
            CP_ASYNC16(st + 0 * TILE_B + o, Ahi + ga);
            CP_ASYNC16(st + 1 * TILE_B + o, Alo + ga);
            CP_ASYNC16(st + 2 * TILE_B + o, whi + gb);
            CP_ASYNC16(st + 3 * TILE_B + o, wlo + gb);
        }
    };

    load_chunk(0, 0); CP_COMMIT();
    load_chunk(1, 1); CP_COMMIT();

    for (int c = 0; c < NCHUNK; c++) {
        const int buf = c & 1;
        CP_WAIT1();
        __syncthreads();

        const uint32_t st = sb + buf * STAGE_B;
        const uint32_t sAh = st + 0 * TILE_B, sAl = st + 1 * TILE_B;
        const uint32_t sBh = st + 2 * TILE_B, sBl = st + 3 * TILE_B;

#pragma unroll
        for (int ks = 0; ks < 2; ks++) {
            uint32_t ah[2][4], al[2][4];
#pragma unroll
            for (int mf = 0; mf < 2; mf++) {
                int ra = wm * 32 + mf * 16 + (lane & 15);
                int ca = ks * 2 + (lane >> 4);
                uint32_t o = sw_off(ra, ca);
                LDSM_X4(ah[mf][0], ah[mf][1], ah[mf][2], ah[mf][3], sAh + o);
                LDSM_X4(al[mf][0], al[mf][1], al[mf][2], al[mf][3], sAl + o);
            }
#pragma unroll
            for (int nfp = 0; nfp < 4; nfp++) {
                int rb = wn * 64 + nfp * 16 + ((lane >> 4) & 1) * 8 + (lane & 7);
                int cbk = ks * 2 + ((lane >> 3) & 1);
                uint32_t o = sw_off(rb, cbk);
                uint32_t bh[4], bl[4];
                LDSM_X4(bh[0], bh[1], bh[2], bh[3], sBh + o);
                LDSM_X4(bl[0], bl[1], bl[2], bl[3], sBl + o);
#pragma unroll
                for (int sub = 0; sub < 2; sub++) {
                    int nf = nfp * 2 + sub;
                    uint32_t h0 = bh[sub * 2], h1 = bh[sub * 2 + 1];
                    uint32_t l0 = bl[sub * 2], l1 = bl[sub * 2 + 1];
#pragma unroll
                    for (int mf = 0; mf < 2; mf++) {
                        MMA_BF16(acc[mf][nf], ah[mf], h0, h1);
                        MMA_BF16(acc[mf][nf], ah[mf], l0, l1);
                        MMA_BF16(acc[mf][nf], al[mf], h0, h1);
                    }
                }
            }
        }
        __syncthreads();
        if (c + 2 < NCHUNK) load_chunk(buf, c + 2);
        CP_COMMIT();
    }

    const int g = lane >> 2, t = lane & 3;
    if (Cf) {
        float* C = Cf + (size_t)z * cstride;
#pragma unroll
        for (int mf = 0; mf < 2; mf++)
#pragma unroll
            for (int nf = 0; nf < 8; nf++) {
                int row = m0 + wm * 32 + mf * 16 + g;
                int col = n0 + wn * 64 + nf * 8 + 2 * t;
                float* p0 = C + (size_t)row * DM + col;
                float* p1 = C + (size_t)(row + 8) * DM + col;
                p0[0] = acc[mf][nf][0]; p0[1] = acc[mf][nf][1];
                p1[0] = acc[mf][nf][2]; p1[1] = acc[mf][nf][3];
            }
    } else if (z == 2) {
        // V slice -> fp16 single
#pragma unroll
        for (int mf = 0; mf < 2; mf++)
#pragma unroll
            for (int nf = 0; nf < 8; nf++) {
                int row = m0 + wm * 32 + mf * 16 + g;
                int col = n0 + wn * 64 + nf * 8 + 2 * t;
                *(uint32_t*)(V16 + (size_t)row * DM + col) =
                    pack_h2(acc[mf][nf][0], acc[mf][nf][1]);
                *(uint32_t*)(V16 + (size_t)(row + 8) * DM + col) =
                    pack_h2(acc[mf][nf][2], acc[mf][nf][3]);
            }
    } else {
        __nv_bfloat16* CH = Chi + (size_t)z * cstride;
        __nv_bfloat16* CL = Clo + (size_t)z * cstride;
#pragma unroll
        for (int mf = 0; mf < 2; mf++)
#pragma unroll
            for (int nf = 0; nf < 8; nf++) {
                int row = m0 + wm * 32 + mf * 16 + g;
                int col = n0 + wn * 64 + nf * 8 + 2 * t;
                uint32_t h0, l0, h1, l1;
                split2(acc[mf][nf][0], acc[mf][nf][1], h0, l0);
                split2(acc[mf][nf][2], acc[mf][nf][3], h1, l1);
                *(uint32_t*)(CH + (size_t)row * DM + col) = h0;
                *(uint32_t*)(CL + (size_t)row * DM + col) = l0;
                *(uint32_t*)(CH + (size_t)(row + 8) * DM + col) = h1;
                *(uint32_t*)(CL + (size_t)(row + 8) * DM + col) = l1;
            }
    }
}

// ---------------------------------------------------------------------------
// Tensor-core causal flash attention.
// Q tile 128 rows, KV tile 64, 8 warps (16 Q rows each).
// QK^T: split-bf16 3-product.  P.V: single fp16 (P fp16 from regs, V fp16).
// Smem: Qh|Ql (16KB ea) + 2-stage {Kh 8K, Kl 8K, Vf 8K} = 80KB dynamic.
// FSW(row,c16) = row*128 + ((c16 ^ (row&7))<<4)  (128B rows).
// ---------------------------------------------------------------------------
#define FSW(row, c16) ((uint32_t)((row) * 128 + ((((c16) ^ ((row) & 7))) << 4)))
#define KVSTAGE_B 24576
#define FA_SMEM (32768 + 2 * KVSTAGE_B)   // 81920

__global__ void __launch_bounds__(256)
flash_mma(void)
{
    extern __shared__ __align__(16) char fsm[];
    const uint32_t sb = smem_u32(fsm);
    const uint32_t sQh = sb, sQl = sb + 16384;

    const int qi = (gridDim.x - 1) - blockIdx.x;   // big tiles first
    const int b  = blockIdx.y >> 4;
    const int h  = blockIdx.y & 15;

    const int tid = threadIdx.x;
    const int w = tid >> 5, lane = tid & 31;

    const size_t MN = (size_t)MROWS * DM;
    const size_t base = (size_t)b * S_LEN * DM + h * DHEAD;
    const __nv_bfloat16* Qh = g_qkvh + base;
    const __nv_bfloat16* Ql = g_qkvl + base;
    const __nv_bfloat16* Kh = g_qkvh + MN + base;
    const __nv_bfloat16* Kl = g_qkvl + MN + base;
    const __half*        Vf = g_vf16 + base;

    const int nchunk = 2 * qi + 2;    // KV chunks of 64 rows

    auto load_kv = [&](int stage, int j) {
        const uint32_t st = sb + 32768 + stage * KVSTAGE_B;
#pragma unroll
        for (int i = 0; i < 2; i++) {
            int idx = tid + i * 256;          // 0..511
            int row = idx >> 3, c16 = idx & 7;
            uint32_t o = FSW(row, c16);
            size_t gmo = (size_t)(j * 64 + row) * DM + c16 * 8;
            CP_ASYNC16(st + 0     + o, Kh + gmo);
            CP_ASYNC16(st + 8192  + o, Kl + gmo);
            CP_ASYNC16(st + 16384 + o, Vf + gmo);
        }
    };

    // prologue: Q tile (128 rows) + KV stage 0, one commit group
#pragma unroll
    for (int i = 0; i < 4; i++) {
        int idx = tid + i * 256;              // 0..1023
        int row = idx >> 3, c16 = idx & 7;
        uint32_t o = FSW(row, c16);
        size_t gmo = (size_t)(qi * 128 + row) * DM + c16 * 8;
        CP_ASYNC16(sQh + o, Qh + gmo);
        CP_ASYNC16(sQl + o, Ql + gmo);
    }
    load_kv(0, 0);
    CP_COMMIT();

    float o_acc[8][4];
#pragma unroll
    for (int i = 0; i < 8; i++)
#pragma unroll
        for (int k = 0; k < 4; k++) o_acc[i][k] = 0.f;
    float m0 = -1e30f, m1 = -1e30f, l0 = 0.f, l1 = 0.f;

    for (int j = 0; j < nchunk; j++) {
        const int buf = j & 1;
        __syncthreads();                    // all warps done with stage buf
        if (j + 1 < nchunk) { load_kv(buf ^ 1, j + 1); CP_COMMIT(); CP_WAIT1(); }
        else                { CP_WAIT0(); }
        __syncthreads();

        const uint32_t st  = sb + 32768 + buf * KVSTAGE_B;
        const uint32_t stKh = st, stKl = st + 8192, stVf = st + 16384;

        // ---- S = Q K^T (split-bf16, 3 products) ----
        float s[8][4];
#pragma unroll
        for (int i = 0; i < 8; i++)
#pragma unroll
            for (int k = 0; k < 4; k++) s[i][k] = 0.f;

#pragma unroll
        for (int ks = 0; ks < 4; ks++) {
            uint32_t ah[4], al[4];
            uint32_t oA = FSW(w * 16 + (lane & 15), ks * 2 + (lane >> 4));
            LDSM_X4(ah[0], ah[1], ah[2], ah[3], sQh + oA);
            LDSM_X4(al[0], al[1], al[2], al[3], sQl + oA);
#pragma unroll
            for (int nfp = 0; nfp < 4; nfp++) {
                uint32_t oB = FSW(nfp * 16 + ((lane >> 4) & 1) * 8 + (lane & 7),
                                  ks * 2 + ((lane >> 3) & 1));
                uint32_t bh[4], bl[4];
                LDSM_X4(bh[0], bh[1], bh[2], bh[3], stKh + oB);
                LDSM_X4(bl[0], bl[1], bl[2], bl[3], stKl + oB);
#pragma unroll
                for (int sub = 0; sub < 2; sub++) {
                    int nf = nfp * 2 + sub;
                    MMA_BF16(s[nf], ah, bh[sub * 2], bh[sub * 2 + 1]);
                    MMA_BF16(s[nf], ah, bl[sub * 2], bl[sub * 2 + 1]);
                    MMA_BF16(s[nf], al, bh[sub * 2], bh[sub * 2 + 1]);
                }
            }
        }

        // ---- scale + causal mask (global row/col compare on tail chunks) ----
        const float scale = 0.125f;   // 1/sqrt(64)
        const int rg = qi * 128 + w * 16 + (lane >> 2);   // global row (c0,c1); +8 for c2,c3
        const int cb = j * 64 + (lane & 3) * 2;           // global col base
        if (j >= 2 * qi) {
#pragma unroll
            for (int nf = 0; nf < 8; nf++) {
                int c0 = cb + nf * 8;
                s[nf][0] = (c0     <= rg    ) ? s[nf][0] * scale : -1e30f;
                s[nf][1] = (c0 + 1 <= rg    ) ? s[nf][1] * scale : -1e30f;
                s[nf][2] = (c0     <= rg + 8) ? s[nf][2] * scale : -1e30f;
                s[nf][3] = (c0 + 1 <= rg + 8) ? s[nf][3] * scale : -1e30f;
            }
        } else {
#pragma unroll
            for (int nf = 0; nf < 8; nf++)
#pragma unroll
                for (int k = 0; k < 4; k++) s[nf][k] *= scale;
        }

        // ---- online softmax (rows rg, rg+8; quad lanes share a row) ----
        float mx0 = s[0][0], mx1 = s[0][2];
#pragma unroll
        for (int nf = 0; nf < 8; nf++) {
            mx0 = fmaxf(mx0, fmaxf(s[nf][0], s[nf][1]));
            mx1 = fmaxf(mx1, fmaxf(s[nf][2], s[nf][3]));
        }
        mx0 = fmaxf(mx0, __shfl_xor_sync(0xffffffffu, mx0, 1));
        mx0 = fmaxf(mx0, __shfl_xor_sync(0xffffffffu, mx0, 2));
        mx1 = fmaxf(mx1, __shfl_xor_sync(0xffffffffu, mx1, 1));
        mx1 = fmaxf(mx1, __shfl_xor_sync(0xffffffffu, mx1, 2));

        float mn0 = fmaxf(m0, mx0), mn1 = fmaxf(m1, mx1);
        float cr0 = __expf(m0 - mn0), cr1 = __expf(m1 - mn1);
        m0 = mn0; m1 = mn1;

        float sum0 = 0.f, sum1 = 0.f;
#pragma unroll
        for (int nf = 0; nf < 8; nf++) {
            s[nf][0] = __expf(s[nf][0] - mn0); sum0 += s[nf][0];
            s[nf][1] = __expf(s[nf][1] - mn0); sum0 += s[nf][1];
            s[nf][2] = __expf(s[nf][2] - mn1); sum1 += s[nf][2];
            s[nf][3] = __expf(s[nf][3] - mn1); sum1 += s[nf][3];
        }
        sum0 += __shfl_xor_sync(0xffffffffu, sum0, 1);
        sum0 += __shfl_xor_sync(0xffffffffu, sum0, 2);
        sum1 += __shfl_xor_sync(0xffffffffu, sum1, 1);
        sum1 += __shfl_xor_sync(0xffffffffu, sum1, 2);
        l0 = l0 * cr0 + sum0;
        l1 = l1 * cr1 + sum1;

#pragma unroll
        for (int nf = 0; nf < 8; nf++) {
            o_acc[nf][0] *= cr0; o_acc[nf][1] *= cr0;
            o_acc[nf][2] *= cr1; o_acc[nf][3] *= cr1;
        }

        // ---- O += P V (single fp16: P packed from regs, V via ldmatrix.trans) ----
#pragma unroll
        for (int ks = 0; ks < 4; ks++) {
            uint32_t pa[4];
            pa[0] = pack_h2(s[2 * ks][0],     s[2 * ks][1]);
            pa[1] = pack_h2(s[2 * ks][2],     s[2 * ks][3]);
            pa[2] = pack_h2(s[2 * ks + 1][0], s[2 * ks + 1][1]);
            pa[3] = pack_h2(s[2 * ks + 1][2], s[2 * ks + 1][3]);
#pragma unroll
            for (int nfp = 0; nfp < 4; nfp++) {
                uint32_t oV = FSW(ks * 16 + ((lane >> 3) & 1) * 8 + (lane & 7),
                                  nfp * 2 + (lane >> 4));
                uint32_t vf[4];
                LDSM_X4_T(vf[0], vf[1], vf[2], vf[3], stVf + oV);
#pragma unroll
                for (int sub = 0; sub < 2; sub++) {
                    int nf = nfp * 2 + sub;
                    MMA_FP16(o_acc[nf], pa, vf[sub * 2], vf[sub * 2 + 1]);
                }
            }
        }
    }

    // ---- epilogue: normalize + split-write bf16 hi/lo to g_ahi/g_alo ----
    const float inv0 = 1.f / l0, inv1 = 1.f / l1;
    const size_t row0 = (size_t)b * S_LEN + qi * 128 + w * 16 + (lane >> 2);
    const int colb = h * 64 + (lane & 3) * 2;
#pragma unroll
    for (int nf = 0; nf < 8; nf++) {
        int col = colb + nf * 8;
        uint32_t h0, l0b, h1, l1b;
        split2(o_acc[nf][0] * inv0, o_acc[nf][1] * inv0, h0, l0b);
        split2(o_acc[nf][2] * inv1, o_acc[nf][3] * inv1, h1, l1b);
        *(uint32_t*)(g_ahi + row0 * DM + col) = h0;
        *(uint32_t*)(g_alo + row0 * DM + col) = l0b;
        *(uint32_t*)(g_ahi + (row0 + 8) * DM + col) = h1;
        *(uint32_t*)(g_alo + (row0 + 8) * DM + col) = l1b;
    }
}

// ---------------------------------------------------------------------------
extern "C" void kernel_launch(void* const* d_in, const int* in_sizes, int n_in,
                              void* d_out, int out_size)
{
    (void)in_sizes; (void)n_in; (void)out_size;
    const float* x  = (const float*)d_in[0];
    const float* qw = (const float*)d_in[1];
    const float* kw = (const float*)d_in[2];
    const float* vw = (const float*)d_in[3];
    const float* ow = (const float*)d_in[4];
    float* out = (float*)d_out;

    cudaFuncSetAttribute(gemm_mma, cudaFuncAttributeMaxDynamicSharedMemorySize, GEMM_SMEM);
    cudaFuncSetAttribute(flash_mma, cudaFuncAttributeMaxDynamicSharedMemorySize, FA_SMEM);

    __nv_bfloat16 *xhi, *xlo, *whi, *wlo, *ahi, *alo, *qkvh, *qkvl;
    __half* vf16;
    cudaGetSymbolAddress((void**)&xhi, g_xhi);
    cudaGetSymbolAddress((void**)&xlo, g_xlo);
    cudaGetSymbolAddress((void**)&whi, g_whi);
    cudaGetSymbolAddress((void**)&wlo, g_wlo);
    cudaGetSymbolAddress((void**)&ahi, g_ahi);
    cudaGetSymbolAddress((void**)&alo, g_alo);
    cudaGetSymbolAddress((void**)&qkvh, g_qkvh);
    cudaGetSymbolAddress((void**)&qkvl, g_qkvl);
    cudaGetSymbolAddress((void**)&vf16, g_vf16);

    const int nx4 = MROWS * DM / 4;
    const int nw4 = DM * DM / 4;

    // 1) split-convert input + weights
    cvt_split<<<(nx4 + 255) / 256, 256>>>(x, xhi, xlo, nx4);
    cvt_split<<<(nw4 + 255) / 256, 256>>>(qw, whi + 0ul * DM * DM, wlo + 0ul * DM * DM, nw4);
    cvt_split<<<(nw4 + 255) / 256, 256>>>(kw, whi + 1ul * DM * DM, wlo + 1ul * DM * DM, nw4);
    cvt_split<<<(nw4 + 255) / 256, 256>>>(vw, whi + 2ul * DM * DM, wlo + 2ul * DM * DM, nw4);
    cvt_split<<<(nw4 + 255) / 256, 256>>>(ow, whi + 3ul * DM * DM, wlo + 3ul * DM * DM, nw4);

    // 2) QKV projection: Q,K -> split bf16; V -> fp16 single
    dim3 gq(DM / 128, MROWS / 128, 3);
    gemm_mma<<<gq, 256, GEMM_SMEM>>>(xhi, xlo, whi, wlo,
                                     nullptr, qkvh, qkvl, vf16,
                                     (long)DM * DM, (long)MROWS * DM);

    // 3) tensor-core causal flash attention -> split bf16 att
    dim3 ga(S_LEN / 128, BATCHN * NHEAD, 1);
    flash_mma<<<ga, 256, FA_SMEM>>>();

    // 4) O projection -> fp32 final output
    dim3 go(DM / 128, MROWS / 128, 1);
    gemm_mma<<<go, 256, GEMM_SMEM>>>(ahi, alo, whi + 3ul * DM * DM, wlo + 3ul * DM * DM,
                                     out, nullptr, nullptr, nullptr, 0L, 0L);
}

// round 7
// speedup vs baseline: 4.8247x; 1.1637x over previous
#include <cuda_runtime.h>
#include <cuda_bf16.h>
#include <cuda_fp16.h>
#include <cstdint>
#include <math.h>

// Problem constants
#define S_LEN 2048
#define BATCHN 2
#define DM 1024
#define NHEAD 16
#define DHEAD 64
#define MROWS (BATCHN * S_LEN)   // 4096
#define MN ((size_t)MROWS * DM)

// ---------------------------------------------------------------------------
// Scratch (device globals: allocation-free rule)  — all fp16 now
// ---------------------------------------------------------------------------
__device__ __half g_h16[(size_t)3 * MN];   // Q | K(hi) | V
__device__ __half g_kl16[MN];              // K lo
__device__ __half g_x16[MN];               // x truncated fp16
__device__ __half g_wh16[(size_t)4 * DM * DM];  // q,k,v,o weight hi
__device__ __half g_wl16[(size_t)4 * DM * DM];  // q,k,v,o weight lo
__device__ __half g_ah16[MN];              // attention out hi
__device__ __half g_al16[MN];              // attention out lo

// ---------------------------------------------------------------------------
// PTX helpers — sm_80+ only (plain compute_103 target: no tcgen05)
// ---------------------------------------------------------------------------
__device__ __forceinline__ uint32_t smem_u32(const void* p) {
    uint32_t a;
    asm("{ .reg .u64 t; cvta.to.shared.u64 t, %1; cvt.u32.u64 %0, t; }" : "=r"(a) : "l"(p));
    return a;
}

#define LDSM_X4(r0, r1, r2, r3, addr) \
    asm volatile("ldmatrix.sync.aligned.m8n8.x4.shared.b16 {%0,%1,%2,%3}, [%4];" \
                 : "=r"(r0), "=r"(r1), "=r"(r2), "=r"(r3) : "r"(addr))

#define LDSM_X4_T(r0, r1, r2, r3, addr) \
    asm volatile("ldmatrix.sync.aligned.m8n8.x4.trans.shared.b16 {%0,%1,%2,%3}, [%4];" \
                 : "=r"(r0), "=r"(r1), "=r"(r2), "=r"(r3) : "r"(addr))

#define MMA_FP16(c, a, b0, b1) \
    asm volatile("mma.sync.aligned.m16n8k16.row.col.f32.f16.f16.f32 " \
                 "{%0,%1,%2,%3}, {%4,%5,%6,%7}, {%8,%9}, {%0,%1,%2,%3};" \
                 : "+f"((c)[0]), "+f"((c)[1]), "+f"((c)[2]), "+f"((c)[3]) \
                 : "r"((a)[0]), "r"((a)[1]), "r"((a)[2]), "r"((a)[3]), "r"(b0), "r"(b1))

#define CP_ASYNC16(saddr, gaddr) \
    asm volatile("cp.async.cg.shared.global [%0], [%1], 16;" :: "r"(saddr), "l"(gaddr))
#define CP_COMMIT() asm volatile("cp.async.commit_group;" ::: "memory")
#define CP_WAIT0()  asm volatile("cp.async.wait_group 0;" ::: "memory")
#define CP_WAIT1()  asm volatile("cp.async.wait_group 1;" ::: "memory")

__device__ __forceinline__ uint32_t pack_h2(float x, float y) {
    __half2 h = __floats2half2_rn(x, y);
    return *(uint32_t*)&h;
}
// fp16 hi/lo split of two fp32 (packed pairs)
__device__ __forceinline__ void split2h(float x, float y, uint32_t& hi, uint32_t& lo) {
    __half2 h = __floats2half2_rn(x, y);
    __half2 l = __floats2half2_rn(x - __half2float(h.x), y - __half2float(h.y));
    hi = *(uint32_t*)&h;
    lo = *(uint32_t*)&l;
}

// ---------------------------------------------------------------------------
// fp32 -> fp16 truncate (x)
// ---------------------------------------------------------------------------
__global__ void cvt_h(const float* __restrict__ src, __half* __restrict__ dst, int n4)
{
    int i = blockIdx.x * blockDim.x + threadIdx.x;
    if (i >= n4) return;
    float4 v = ((const float4*)src)[i];
    ((uint32_t*)dst)[2 * i + 0] = pack_h2(v.x, v.y);
    ((uint32_t*)dst)[2 * i + 1] = pack_h2(v.z, v.w);
}

// fp32 -> fp16 hi/lo split, 4 weight tensors via z
__global__ void cvt_w4(const float* __restrict__ s0, const float* __restrict__ s1,
                       const float* __restrict__ s2, const float* __restrict__ s3,
                       __half* __restrict__ hi, __half* __restrict__ lo, int n4)
{
    int i = blockIdx.x * blockDim.x + threadIdx.x;
    if (i >= n4) return;
    int z = blockIdx.z;
    const float* src = (z == 0) ? s0 : (z == 1) ? s1 : (z == 2) ? s2 : s3;
    __half* h = hi + (size_t)z * DM * DM;
    __half* l = lo + (size_t)z * DM * DM;
    float4 v = ((const float4*)src)[i];
    uint32_t h0, l0, h1, l1;
    split2h(v.x, v.y, h0, l0);
    split2h(v.z, v.w, h1, l1);
    ((uint32_t*)h)[2 * i + 0] = h0;
    ((uint32_t*)h)[2 * i + 1] = h1;
    ((uint32_t*)l)[2 * i + 0] = l0;
    ((uint32_t*)l)[2 * i + 1] = l1;
}

// ---------------------------------------------------------------------------
// mma.sync fp16 NT GEMM: C[m,n] = sum_k A[m,k] * W[n,k]
// THREE=false: 2 products  A_h*(W_h + W_l)          (A = single fp16)
// THREE=true : 3 products  Ah*Wh + Ah*Wl + Al*Wh    (A = fp16 hi/lo)
// Epilogue: Cf -> fp32 | else fp16 hi to Chi (+lo to Clo when z==1).
// ---------------------------------------------------------------------------
#define BK 32
#define TILE_B (128 * BK * 2)
#define STAGE_B (4 * TILE_B)
#define GEMM_SMEM (2 * STAGE_B)
#define NCHUNK (DM / BK)

__device__ __forceinline__ uint32_t sw_off(int row, int c16) {
    return (uint32_t)(row * 64 + ((c16 ^ ((row >> 1) & 3)) << 4));
}

template <bool THREE>
__global__ void __launch_bounds__(256)
gemm_h(const __half* __restrict__ Ah, const __half* __restrict__ Al,
       const __half* __restrict__ Wh, const __half* __restrict__ Wl,
       float* __restrict__ Cf, __half* __restrict__ Chi, __half* __restrict__ Clo,
       long wstride, long cstride)
{
    extern __shared__ __align__(16) char smem[];
    const uint32_t sb = smem_u32(smem);
    const int tid = threadIdx.x;
    const int wid = tid >> 5, lane = tid & 31;
    const int z = blockIdx.z;
    const __half* wh = Wh + (size_t)z * wstride;
    const __half* wl = Wl + (size_t)z * wstride;
    const int m0 = blockIdx.y * 128;
    const int n0 = blockIdx.x * 128;

    const int wm = wid & 3;
    const int wn = wid >> 2;

    float acc[2][8][4];
#pragma unroll
    for (int i = 0; i < 2; i++)
#pragma unroll
        for (int j = 0; j < 8; j++)
#pragma unroll
            for (int k = 0; k < 4; k++) acc[i][j][k] = 0.f;

    const int r0q = tid >> 2, c0q = tid & 3;
    const int r1q = (tid + 256) >> 2, c1q = tid & 3;

    auto load_chunk = [&](int s, int c) {
        const uint32_t st = sb + s * STAGE_B;
        const int k0 = c * BK;
        {
            uint32_t o = sw_off(r0q, c0q);
            size_t ga = (size_t)(m0 + r0q) * DM + k0 + c0q * 8;
            size_t gb = (size_t)(n0 + r0q) * DM + k0 + c0q * 8;
            CP_ASYNC16(st + 0 * TILE_B + o, Ah + ga);
            if (THREE) CP_ASYNC16(st + 1 * TILE_B + o, Al + ga);
            CP_ASYNC16(st + 2 * TILE_B + o, wh + gb);
            CP_ASYNC16(st + 3 * TILE_B + o, wl + gb);
        }
        {
            uint32_t o = sw_off(r1q, c1q);
            size_t ga = (size_t)(m0 + r1q) * DM + k0 + c1q * 8;
            size_t gb = (size_t)(n0 + r1q) * DM + k0 + c1q * 8;
            CP_ASYNC16(st + 0 * TILE_B + o, Ah + ga);
            if (THREE) CP_ASYNC16(st + 1 * TILE_B + o, Al + ga);
            CP_ASYNC16(st + 2 * TILE_B + o, wh + gb);
            CP_ASYNC16(st + 3 * TILE_B + o, wl + gb);
        }
    };

    load_chunk(0, 0); CP_COMMIT();
    load_chunk(1, 1); CP_COMMIT();

    for (int c = 0; c < NCHUNK; c++) {
        const int buf = c & 1;
        CP_WAIT1();
        __syncthreads();

        const uint32_t st = sb + buf * STAGE_B;
        const uint32_t sAh = st + 0 * TILE_B, sAl = st + 1 * TILE_B;
        const uint32_t sBh = st + 2 * TILE_B, sBl = st + 3 * TILE_B;

#pragma unroll
        for (int ks = 0; ks < 2; ks++) {
            uint32_t ah[2][4], al[2][4];
#pragma unroll
            for (int mf = 0; mf < 2; mf++) {
                int ra = wm * 32 + mf * 16 + (lane & 15);
                int ca = ks * 2 + (lane >> 4);
                uint32_t o = sw_off(ra, ca);
                LDSM_X4(ah[mf][0], ah[mf][1], ah[mf][2], ah[mf][3], sAh + o);
                if (THREE) LDSM_X4(al[mf][0], al[mf][1], al[mf][2], al[mf][3], sAl + o);
            }
#pragma unroll
            for (int nfp = 0; nfp < 4; nfp++) {
                int rb = wn * 64 + nfp * 16 + ((lane >> 4) & 1) * 8 + (lane & 7);
                int cbk = ks * 2 + ((lane >> 3) & 1);
                uint32_t o = sw_off(rb, cbk);
                uint32_t bh[4], bl[4];
                LDSM_X4(bh[0], bh[1], bh[2], bh[3], sBh + o);
                LDSM_X4(bl[0], bl[1], bl[2], bl[3], sBl + o);
#pragma unroll
                for (int sub = 0; sub < 2; sub++) {
                    int nf = nfp * 2 + sub;
                    uint32_t h0 = bh[sub * 2], h1 = bh[sub * 2 + 1];
                    uint32_t l0 = bl[sub * 2], l1 = bl[sub * 2 + 1];
#pragma unroll
                    for (int mf = 0; mf < 2; mf++) {
                        MMA_FP16(acc[mf][nf], ah[mf], h0, h1);
                        MMA_FP16(acc[mf][nf], ah[mf], l0, l1);
                        if (THREE) MMA_FP16(acc[mf][nf], al[mf], h0, h1);
                    }
                }
            }
        }
        __syncthreads();
        if (c + 2 < NCHUNK) load_chunk(buf, c + 2);
        CP_COMMIT();
    }

    const int g = lane >> 2, t = lane & 3;
    if (Cf) {
        float* C = Cf + (size_t)z * cstride;
#pragma unroll
        for (int mf = 0; mf < 2; mf++)
#pragma unroll
            for (int nf = 0; nf < 8; nf++) {
                int row = m0 + wm * 32 + mf * 16 + g;
                int col = n0 + wn * 64 + nf * 8 + 2 * t;
                float* p0 = C + (size_t)row * DM + col;
                float* p1 = C + (size_t)(row + 8) * DM + col;
                p0[0] = acc[mf][nf][0]; p0[1] = acc[mf][nf][1];
                p1[0] = acc[mf][nf][2]; p1[1] = acc[mf][nf][3];
            }
    } else {
        __half* CH = Chi + (size_t)z * cstride;
        const bool wrlo = (z == 1);   // K gets hi/lo; Q,V single fp16
#pragma unroll
        for (int mf = 0; mf < 2; mf++)
#pragma unroll
            for (int nf = 0; nf < 8; nf++) {
                int row = m0 + wm * 32 + mf * 16 + g;
                int col = n0 + wn * 64 + nf * 8 + 2 * t;
                uint32_t h0, l0, h1, l1;
                split2h(acc[mf][nf][0], acc[mf][nf][1], h0, l0);
                split2h(acc[mf][nf][2], acc[mf][nf][3], h1, l1);
                *(uint32_t*)(CH + (size_t)row * DM + col) = h0;
                *(uint32_t*)(CH + (size_t)(row + 8) * DM + col) = h1;
                if (wrlo) {
                    *(uint32_t*)(Clo + (size_t)row * DM + col) = l0;
                    *(uint32_t*)(Clo + (size_t)(row + 8) * DM + col) = l1;
                }
            }
    }
}

// ---------------------------------------------------------------------------
// Tensor-core causal flash attention (all fp16 operands, fp32 accum).
// Q tile 128 rows, KV tile 64, 8 warps.
// QK^T: 2-product (Q single, K hi/lo).  P.V: single fp16.
// Smem: Q 16KB + 2-stage {Kh 8K, Kl 8K, V 8K} = 64KB dynamic.
// ---------------------------------------------------------------------------
#define FSW(row, c16) ((uint32_t)((row) * 128 + ((((c16) ^ ((row) & 7))) << 4)))
#define KVSTAGE_B 24576
#define FA_SMEM (16384 + 2 * KVSTAGE_B)   // 65536

__global__ void __launch_bounds__(256)
flash_mma(void)
{
    extern __shared__ __align__(16) char fsm[];
    const uint32_t sb = smem_u32(fsm);
    const uint32_t sQ = sb;

    const int qi = (gridDim.x - 1) - blockIdx.x;   // big tiles first
    const int b  = blockIdx.y >> 4;
    const int h  = blockIdx.y & 15;

    const int tid = threadIdx.x;
    const int w = tid >> 5, lane = tid & 31;

    const size_t base = (size_t)b * S_LEN * DM + h * DHEAD;
    const __half* Qp  = g_h16 + base;
    const __half* Kh  = g_h16 + MN + base;
    const __half* Kl  = g_kl16 + base;
    const __half* Vf  = g_h16 + 2 * MN + base;

    const int nchunk = 2 * qi + 2;    // KV chunks of 64 rows

    auto load_kv = [&](int stage, int j) {
        const uint32_t st = sb + 16384 + stage * KVSTAGE_B;
#pragma unroll
        for (int i = 0; i < 2; i++) {
            int idx = tid + i * 256;          // 0..511
            int row = idx >> 3, c16 = idx & 7;
            uint32_t o = FSW(row, c16);
            size_t gmo = (size_t)(j * 64 + row) * DM + c16 * 8;
            CP_ASYNC16(st + 0     + o, Kh + gmo);
            CP_ASYNC16(st + 8192  + o, Kl + gmo);
            CP_ASYNC16(st + 16384 + o, Vf + gmo);
        }
    };

    // prologue: Q tile (128 rows x 64 fp16 = 16KB) + KV stage 0
#pragma unroll
    for (int i = 0; i < 4; i++) {
        int idx = tid + i * 256;              // 0..1023
        int row = idx >> 3, c16 = idx & 7;
        uint32_t o = FSW(row, c16);
        size_t gmo = (size_t)(qi * 128 + row) * DM + c16 * 8;
        CP_ASYNC16(sQ + o, Qp + gmo);
    }
    load_kv(0, 0);
    CP_COMMIT();

    float o_acc[8][4];
#pragma unroll
    for (int i = 0; i < 8; i++)
#pragma unroll
        for (int k = 0; k < 4; k++) o_acc[i][k] = 0.f;
    float m0 = -1e30f, m1 = -1e30f, l0 = 0.f, l1 = 0.f;

    for (int j = 0; j < nchunk; j++) {
        const int buf = j & 1;
        __syncthreads();                    // all warps done with stage buf
        if (j + 1 < nchunk) { load_kv(buf ^ 1, j + 1); CP_COMMIT(); CP_WAIT1(); }
        else                { CP_WAIT0(); }
        __syncthreads();

        const uint32_t st  = sb + 16384 + buf * KVSTAGE_B;
        const uint32_t stKh = st, stKl = st + 8192, stVf = st + 16384;

        // ---- S = Q K^T (fp16 2-product: Q*(Kh + Kl)) ----
        float s[8][4];
#pragma unroll
        for (int i = 0; i < 8; i++)
#pragma unroll
            for (int k = 0; k < 4; k++) s[i][k] = 0.f;

#pragma unroll
        for (int ks = 0; ks < 4; ks++) {
            uint32_t qf[4];
            uint32_t oA = FSW(w * 16 + (lane & 15), ks * 2 + (lane >> 4));
            LDSM_X4(qf[0], qf[1], qf[2], qf[3], sQ + oA);
#pragma unroll
            for (int nfp = 0; nfp < 4; nfp++) {
                uint32_t oB = FSW(nfp * 16 + ((lane >> 4) & 1) * 8 + (lane & 7),
                                  ks * 2 + ((lane >> 3) & 1));
                uint32_t bh[4], bl[4];
                LDSM_X4(bh[0], bh[1], bh[2], bh[3], stKh + oB);
                LDSM_X4(bl[0], bl[1], bl[2], bl[3], stKl + oB);
#pragma unroll
                for (int sub = 0; sub < 2; sub++) {
                    int nf = nfp * 2 + sub;
                    MMA_FP16(s[nf], qf, bh[sub * 2], bh[sub * 2 + 1]);
                    MMA_FP16(s[nf], qf, bl[sub * 2], bl[sub * 2 + 1]);
                }
            }
        }

        // ---- scale + causal mask (global row/col compare on tail chunks) ----
        const float scale = 0.125f;   // 1/sqrt(64)
        const int rg = qi * 128 + w * 16 + (lane >> 2);
        const int cb = j * 64 + (lane & 3) * 2;
        if (j >= 2 * qi) {
#pragma unroll
            for (int nf = 0; nf < 8; nf++) {
                int c0 = cb + nf * 8;
                s[nf][0] = (c0     <= rg    ) ? s[nf][0] * scale : -1e30f;
                s[nf][1] = (c0 + 1 <= rg    ) ? s[nf][1] * scale : -1e30f;
                s[nf][2] = (c0     <= rg + 8) ? s[nf][2] * scale : -1e30f;
                s[nf][3] = (c0 + 1 <= rg + 8) ? s[nf][3] * scale : -1e30f;
            }
        } else {
#pragma unroll
            for (int nf = 0; nf < 8; nf++)
#pragma unroll
                for (int k = 0; k < 4; k++) s[nf][k] *= scale;
        }

        // ---- online softmax (rows rg, rg+8; quad lanes share a row) ----
        float mx0 = s[0][0], mx1 = s[0][2];
#pragma unroll
        for (int nf = 0; nf < 8; nf++) {
            mx0 = fmaxf(mx0, fmaxf(s[nf][0], s[nf][1]));
            mx1 = fmaxf(mx1, fmaxf(s[nf][2], s[nf][3]));
        }
        mx0 = fmaxf(mx0, __shfl_xor_sync(0xffffffffu, mx0, 1));
        mx0 = fmaxf(mx0, __shfl_xor_sync(0xffffffffu, mx0, 2));
        mx1 = fmaxf(mx1, __shfl_xor_sync(0xffffffffu, mx1, 1));
        mx1 = fmaxf(mx1, __shfl_xor_sync(0xffffffffu, mx1, 2));

        float mn0 = fmaxf(m0, mx0), mn1 = fmaxf(m1, mx1);
        float cr0 = __expf(m0 - mn0), cr1 = __expf(m1 - mn1);
        m0 = mn0; m1 = mn1;

        float sum0 = 0.f, sum1 = 0.f;
#pragma unroll
        for (int nf = 0; nf < 8; nf++) {
            s[nf][0] = __expf(s[nf][0] - mn0); sum0 += s[nf][0];
            s[nf][1] = __expf(s[nf][1] - mn0); sum0 += s[nf][1];
            s[nf][2] = __expf(s[nf][2] - mn1); sum1 += s[nf][2];
            s[nf][3] = __expf(s[nf][3] - mn1); sum1 += s[nf][3];
        }
        sum0 += __shfl_xor_sync(0xffffffffu, sum0, 1);
        sum0 += __shfl_xor_sync(0xffffffffu, sum0, 2);
        sum1 += __shfl_xor_sync(0xffffffffu, sum1, 1);
        sum1 += __shfl_xor_sync(0xffffffffu, sum1, 2);
        l0 = l0 * cr0 + sum0;
        l1 = l1 * cr1 + sum1;

#pragma unroll
        for (int nf = 0; nf < 8; nf++) {
            o_acc[nf][0] *= cr0; o_acc[nf][1] *= cr0;
            o_acc[nf][2] *= cr1; o_acc[nf][3] *= cr1;
        }

        // ---- O += P V (single fp16) ----
#pragma unroll
        for (int ks = 0; ks < 4; ks++) {
            uint32_t pa[4];
            pa[0] = pack_h2(s[2 * ks][0],     s[2 * ks][1]);
            pa[1] = pack_h2(s[2 * ks][2],     s[2 * ks][3]);
            pa[2] = pack_h2(s[2 * ks + 1][0], s[2 * ks + 1][1]);
            pa[3] = pack_h2(s[2 * ks + 1][2], s[2 * ks + 1][3]);
#pragma unroll
            for (int nfp = 0; nfp < 4; nfp++) {
                uint32_t oV = FSW(ks * 16 + ((lane >> 3) & 1) * 8 + (lane & 7),
                                  nfp * 2 + (lane >> 4));
                uint32_t vf[4];
                LDSM_X4_T(vf[0], vf[1], vf[2], vf[3], stVf + oV);
#pragma unroll
                for (int sub = 0; sub < 2; sub++) {
                    int nf = nfp * 2 + sub;
                    MMA_FP16(o_acc[nf], pa, vf[sub * 2], vf[sub * 2 + 1]);
                }
            }
        }
    }

    // ---- epilogue: normalize + fp16 hi/lo split-write ----
    const float inv0 = 1.f / l0, inv1 = 1.f / l1;
    const size_t row0 = (size_t)b * S_LEN + qi * 128 + w * 16 + (lane >> 2);
    const int colb = h * 64 + (lane & 3) * 2;
#pragma unroll
    for (int nf = 0; nf < 8; nf++) {
        int col = colb + nf * 8;
        uint32_t h0, l0b, h1, l1b;
        split2h(o_acc[nf][0] * inv0, o_acc[nf][1] * inv0, h0, l0b);
        split2h(o_acc[nf][2] * inv1, o_acc[nf][3] * inv1, h1, l1b);
        *(uint32_t*)(g_ah16 + row0 * DM + col) = h0;
        *(uint32_t*)(g_al16 + row0 * DM + col) = l0b;
        *(uint32_t*)(g_ah16 + (row0 + 8) * DM + col) = h1;
        *(uint32_t*)(g_al16 + (row0 + 8) * DM + col) = l1b;
    }
}

// ---------------------------------------------------------------------------
extern "C" void kernel_launch(void* const* d_in, const int* in_sizes, int n_in,
                              void* d_out, int out_size)
{
    (void)in_sizes; (void)n_in; (void)out_size;
    const float* x  = (const float*)d_in[0];
    const float* qw = (const float*)d_in[1];
    const float* kw = (const float*)d_in[2];
    const float* vw = (const float*)d_in[3];
    const float* ow = (const float*)d_in[4];
    float* out = (float*)d_out;

    cudaFuncSetAttribute(gemm_h<false>, cudaFuncAttributeMaxDynamicSharedMemorySize, GEMM_SMEM);
    cudaFuncSetAttribute(gemm_h<true>,  cudaFuncAttributeMaxDynamicSharedMemorySize, GEMM_SMEM);
    cudaFuncSetAttribute(flash_mma, cudaFuncAttributeMaxDynamicSharedMemorySize, FA_SMEM);

    __half *x16, *wh16, *wl16, *h16, *kl16, *ah16, *al16;
    cudaGetSymbolAddress((void**)&x16, g_x16);
    cudaGetSymbolAddress((void**)&wh16, g_wh16);
    cudaGetSymbolAddress((void**)&wl16, g_wl16);
    cudaGetSymbolAddress((void**)&h16, g_h16);
    cudaGetSymbolAddress((void**)&kl16, g_kl16);
    cudaGetSymbolAddress((void**)&ah16, g_ah16);
    cudaGetSymbolAddress((void**)&al16, g_al16);

    const int nx4 = MROWS * DM / 4;
    const int nw4 = DM * DM / 4;

    // 1) convert: x -> fp16; 4 weights -> fp16 hi/lo (one z-fused launch)
    cvt_h<<<(nx4 + 255) / 256, 256>>>(x, x16, nx4);
    dim3 gw((nw4 + 255) / 256, 1, 4);
    cvt_w4<<<gw, 256>>>(qw, kw, vw, ow, wh16, wl16, nw4);

    // 2) QKV projection (2-product): Q,V -> fp16 single; K -> fp16 hi/lo
    dim3 gq(DM / 128, MROWS / 128, 3);
    gemm_h<false><<<gq, 256, GEMM_SMEM>>>(x16, nullptr, wh16, wl16,
                                          nullptr, h16, kl16,
                                          (long)DM * DM, (long)MN);

    // 3) causal flash attention -> att fp16 hi/lo
    dim3 ga(S_LEN / 128, BATCHN * NHEAD, 1);
    flash_mma<<<ga, 256, FA_SMEM>>>();

    // 4) O projection (3-product, accuracy hedge) -> fp32 final output
    dim3 go(DM / 128, MROWS / 128, 1);
    gemm_h<true><<<go, 256, GEMM_SMEM>>>(ah16, al16, wh16 + 3ul * DM * DM, wl16 + 3ul * DM * DM,
                                         out, nullptr, nullptr, 0L, 0L);
}

// round 9
// speedup vs baseline: 5.6235x; 1.1656x over previous
#include <cuda_runtime.h>
#include <cuda_fp16.h>
#include <cstdint>
#include <math.h>

// Problem constants
#define S_LEN 2048
#define BATCHN 2
#define DM 1024
#define NHEAD 16
#define DHEAD 64
#define MROWS (BATCHN * S_LEN)   // 4096
#define MN ((size_t)MROWS * DM)

// ---------------------------------------------------------------------------
// Scratch (device globals: allocation-free rule) — all fp16 single except W
// ---------------------------------------------------------------------------
__device__ __half g_h16[(size_t)3 * MN];        // Q | K | V  (fp16)
__device__ __half g_x16[MN];                    // x truncated fp16
__device__ __half g_wh16[(size_t)4 * DM * DM];  // q,k,v,o weight hi
__device__ __half g_wl16[(size_t)4 * DM * DM];  // q,k,v,o weight lo
__device__ __half g_a16[MN];                    // attention out fp16

// ---------------------------------------------------------------------------
// PTX helpers — sm_80+ only (plain compute_103 target: no tcgen05)
// ---------------------------------------------------------------------------
__device__ __forceinline__ uint32_t smem_u32(const void* p) {
    uint32_t a;
    asm("{ .reg .u64 t; cvta.to.shared.u64 t, %1; cvt.u32.u64 %0, t; }" : "=r"(a) : "l"(p));
    return a;
}

#define LDSM_X4(r0, r1, r2, r3, addr) \
    asm volatile("ldmatrix.sync.aligned.m8n8.x4.shared.b16 {%0,%1,%2,%3}, [%4];" \
                 : "=r"(r0), "=r"(r1), "=r"(r2), "=r"(r3) : "r"(addr))

#define LDSM_X4_T(r0, r1, r2, r3, addr) \
    asm volatile("ldmatrix.sync.aligned.m8n8.x4.trans.shared.b16 {%0,%1,%2,%3}, [%4];" \
                 : "=r"(r0), "=r"(r1), "=r"(r2), "=r"(r3) : "r"(addr))

#define MMA_FP16(c, a, b0, b1) \
    asm volatile("mma.sync.aligned.m16n8k16.row.col.f32.f16.f16.f32 " \
                 "{%0,%1,%2,%3}, {%4,%5,%6,%7}, {%8,%9}, {%0,%1,%2,%3};" \
                 : "+f"((c)[0]), "+f"((c)[1]), "+f"((c)[2]), "+f"((c)[3]) \
                 : "r"((a)[0]), "r"((a)[1]), "r"((a)[2]), "r"((a)[3]), "r"(b0), "r"(b1))

#define CP_ASYNC16(saddr, gaddr) \
    asm volatile("cp.async.cg.shared.global [%0], [%1], 16;" :: "r"(saddr), "l"(gaddr))
#define CP_COMMIT() asm volatile("cp.async.commit_group;" ::: "memory")
#define CP_WAIT0()  asm volatile("cp.async.wait_group 0;" ::: "memory")
#define CP_WAIT1()  asm volatile("cp.async.wait_group 1;" ::: "memory")

__device__ __forceinline__ uint32_t pack_h2(float x, float y) {
    __half2 h = __floats2half2_rn(x, y);
    return *(uint32_t*)&h;
}
__device__ __forceinline__ void split2h(float x, float y, uint32_t& hi, uint32_t& lo) {
    __half2 h = __floats2half2_rn(x, y);
    __half2 l = __floats2half2_rn(x - __half2float(h.x), y - __half2float(h.y));
    hi = *(uint32_t*)&h;
    lo = *(uint32_t*)&l;
}

// ---------------------------------------------------------------------------
// fp32 -> fp16 truncate (x)
// ---------------------------------------------------------------------------
__global__ void cvt_h(const float* __restrict__ src, __half* __restrict__ dst, int n4)
{
    int i = blockIdx.x * blockDim.x + threadIdx.x;
    if (i >= n4) return;
    float4 v = ((const float4*)src)[i];
    ((uint32_t*)dst)[2 * i + 0] = pack_h2(v.x, v.y);
    ((uint32_t*)dst)[2 * i + 1] = pack_h2(v.z, v.w);
}

// fp32 -> fp16 hi/lo split, 4 weight tensors via z
__global__ void cvt_w4(const float* __restrict__ s0, const float* __restrict__ s1,
                       const float* __restrict__ s2, const float* __restrict__ s3,
                       __half* __restrict__ hi, __half* __restrict__ lo, int n4)
{
    int i = blockIdx.x * blockDim.x + threadIdx.x;
    if (i >= n4) return;
    int z = blockIdx.z;
    const float* src = (z == 0) ? s0 : (z == 1) ? s1 : (z == 2) ? s2 : s3;
    __half* h = hi + (size_t)z * DM * DM;
    __half* l = lo + (size_t)z * DM * DM;
    float4 v = ((const float4*)src)[i];
    uint32_t h0, l0, h1, l1;
    split2h(v.x, v.y, h0, l0);
    split2h(v.z, v.w, h1, l1);
    ((uint32_t*)h)[2 * i + 0] = h0;
    ((uint32_t*)h)[2 * i + 1] = h1;
    ((uint32_t*)l)[2 * i + 0] = l0;
    ((uint32_t*)l)[2 * i + 1] = l1;
}

// ---------------------------------------------------------------------------
// mma.sync fp16 NT GEMM: C[m,n] = sum_k A[m,k] * W[n,k],  2 products:
// C = A * (W_h + W_l), A single fp16, fp32 accumulate.
// Epilogue: Cf -> fp32, else fp16 single to Ch.
// ---------------------------------------------------------------------------
#define BK 32
#define TILE_B (128 * BK * 2)
#define STAGE_B (4 * TILE_B)
#define GEMM_SMEM (2 * STAGE_B)
#define NCHUNK (DM / BK)

__device__ __forceinline__ uint32_t sw_off(int row, int c16) {
    return (uint32_t)(row * 64 + ((c16 ^ ((row >> 1) & 3)) << 4));
}

__global__ void __launch_bounds__(256)
gemm_h(const __half* __restrict__ Ah,
       const __half* __restrict__ Wh, const __half* __restrict__ Wl,
       float* __restrict__ Cf, __half* __restrict__ Ch,
       long wstride, long cstride)
{
    extern __shared__ __align__(16) char smem[];
    const uint32_t sb = smem_u32(smem);
    const int tid = threadIdx.x;
    const int wid = tid >> 5, lane = tid & 31;
    const int z = blockIdx.z;
    const __half* wh = Wh + (size_t)z * wstride;
    const __half* wl = Wl + (size_t)z * wstride;
    const int m0 = blockIdx.y * 128;
    const int n0 = blockIdx.x * 128;

    const int wm = wid & 3;
    const int wn = wid >> 2;

    float acc[2][8][4];
#pragma unroll
    for (int i = 0; i < 2; i++)
#pragma unroll
        for (int j = 0; j < 8; j++)
#pragma unroll
            for (int k = 0; k < 4; k++) acc[i][j][k] = 0.f;

    const int r0q = tid >> 2, c0q = tid & 3;
    const int r1q = (tid + 256) >> 2, c1q = tid & 3;

    auto load_chunk = [&](int s, int c) {
        const uint32_t st = sb + s * STAGE_B;
        const int k0 = c * BK;
        {
            uint32_t o = sw_off(r0q, c0q);
            size_t ga = (size_t)(m0 + r0q) * DM + k0 + c0q * 8;
            size_t gb = (size_t)(n0 + r0q) * DM + k0 + c0q * 8;
            CP_ASYNC16(st + 0 * TILE_B + o, Ah + ga);
            CP_ASYNC16(st + 2 * TILE_B + o, wh + gb);
            CP_ASYNC16(st + 3 * TILE_B + o, wl + gb);
        }
        {
            uint32_t o = sw_off(r1q, c1q);
            size_t ga = (size_t)(m0 + r1q) * DM + k0 + c1q * 8;
            size_t gb = (size_t)(n0 + r1q) * DM + k0 + c1q * 8;
            CP_ASYNC16(st + 0 * TILE_B + o, Ah + ga);
            CP_ASYNC16(st + 2 * TILE_B + o, wh + gb);
            CP_ASYNC16(st + 3 * TILE_B + o, wl + gb);
        }
    };

    load_chunk(0, 0); CP_COMMIT();
    load_chunk(1, 1); CP_COMMIT();

    for (int c = 0; c < NCHUNK; c++) {
        const int buf = c & 1;
        CP_WAIT1();
        __syncthreads();

        const uint32_t st = sb + buf * STAGE_B;
        const uint32_t sAh = st + 0 * TILE_B;
        const uint32_t sBh = st + 2 * TILE_B, sBl = st + 3 * TILE_B;

#pragma unroll
        for (int ks = 0; ks < 2; ks++) {
            uint32_t ah[2][4];
#pragma unroll
            for (int mf = 0; mf < 2; mf++) {
                int ra = wm * 32 + mf * 16 + (lane & 15);
                int ca = ks * 2 + (lane >> 4);
                uint32_t o = sw_off(ra, ca);
                LDSM_X4(ah[mf][0], ah[mf][1], ah[mf][2], ah[mf][3], sAh + o);
            }
#pragma unroll
            for (int nfp = 0; nfp < 4; nfp++) {
                int rb = wn * 64 + nfp * 16 + ((lane >> 4) & 1) * 8 + (lane & 7);
                int cbk = ks * 2 + ((lane >> 3) & 1);
                uint32_t o = sw_off(rb, cbk);
                uint32_t bh[4], bl[4];
                LDSM_X4(bh[0], bh[1], bh[2], bh[3], sBh + o);
                LDSM_X4(bl[0], bl[1], bl[2], bl[3], sBl + o);
#pragma unroll
                for (int sub = 0; sub < 2; sub++) {
                    int nf = nfp * 2 + sub;
                    uint32_t h0 = bh[sub * 2], h1 = bh[sub * 2 + 1];
                    uint32_t l0 = bl[sub * 2], l1 = bl[sub * 2 + 1];
#pragma unroll
                    for (int mf = 0; mf < 2; mf++) {
                        MMA_FP16(acc[mf][nf], ah[mf], h0, h1);
                        MMA_FP16(acc[mf][nf], ah[mf], l0, l1);
                    }
                }
            }
        }
        __syncthreads();
        if (c + 2 < NCHUNK) load_chunk(buf, c + 2);
        CP_COMMIT();
    }

    const int g = lane >> 2, t = lane & 3;
    if (Cf) {
        float* C = Cf + (size_t)z * cstride;
#pragma unroll
        for (int mf = 0; mf < 2; mf++)
#pragma unroll
            for (int nf = 0; nf < 8; nf++) {
                int row = m0 + wm * 32 + mf * 16 + g;
                int col = n0 + wn * 64 + nf * 8 + 2 * t;
                float* p0 = C + (size_t)row * DM + col;
                float* p1 = C + (size_t)(row + 8) * DM + col;
                p0[0] = acc[mf][nf][0]; p0[1] = acc[mf][nf][1];
                p1[0] = acc[mf][nf][2]; p1[1] = acc[mf][nf][3];
            }
    } else {
        __half* CH = Ch + (size_t)z * cstride;
#pragma unroll
        for (int mf = 0; mf < 2; mf++)
#pragma unroll
            for (int nf = 0; nf < 8; nf++) {
                int row = m0 + wm * 32 + mf * 16 + g;
                int col = n0 + wn * 64 + nf * 8 + 2 * t;
                *(uint32_t*)(CH + (size_t)row * DM + col) =
                    pack_h2(acc[mf][nf][0], acc[mf][nf][1]);
                *(uint32_t*)(CH + (size_t)(row + 8) * DM + col) =
                    pack_h2(acc[mf][nf][2], acc[mf][nf][3]);
            }
    }
}

// ---------------------------------------------------------------------------
// Tensor-core causal flash attention — all single fp16 operands, fp32 accum.
// Q tile 128 rows, KV tile 64, 8 warps. QK^T 1 product, P.V 1 product.
// Smem: Q 16KB + 2-stage {K 8K, V 8K} = 48KB dynamic.
// ---------------------------------------------------------------------------
#define FSW(row, c16) ((uint32_t)((row) * 128 + ((((c16) ^ ((row) & 7))) << 4)))
#define KVSTAGE_B 16384
#define FA_SMEM (16384 + 2 * KVSTAGE_B)   // 49152

__global__ void __launch_bounds__(256)
flash_mma(void)
{
    extern __shared__ __align__(16) char fsm[];
    const uint32_t sb = smem_u32(fsm);
    const uint32_t sQ = sb;

    const int qi = (gridDim.x - 1) - blockIdx.x;   // big tiles first
    const int b  = blockIdx.y >> 4;
    const int h  = blockIdx.y & 15;

    const int tid = threadIdx.x;
    const int w = tid >> 5, lane = tid & 31;

    const size_t base = (size_t)b * S_LEN * DM + h * DHEAD;
    const __half* Qp = g_h16 + base;
    const __half* Kp = g_h16 + MN + base;
    const __half* Vp = g_h16 + 2 * MN + base;

    const int nchunk = 2 * qi + 2;    // KV chunks of 64 rows

    auto load_kv = [&](int stage, int j) {
        const uint32_t st = sb + 16384 + stage * KVSTAGE_B;
#pragma unroll
        for (int i = 0; i < 2; i++) {
            int idx = tid + i * 256;          // 0..511
            int row = idx >> 3, c16 = idx & 7;
            uint32_t o = FSW(row, c16);
            size_t gmo = (size_t)(j * 64 + row) * DM + c16 * 8;
            CP_ASYNC16(st + 0    + o, Kp + gmo);
            CP_ASYNC16(st + 8192 + o, Vp + gmo);
        }
    };

    // prologue: Q tile (128 rows x 64 fp16 = 16KB) + KV stage 0
#pragma unroll
    for (int i = 0; i < 4; i++) {
        int idx = tid + i * 256;              // 0..1023
        int row = idx >> 3, c16 = idx & 7;
        uint32_t o = FSW(row, c16);
        size_t gmo = (size_t)(qi * 128 + row) * DM + c16 * 8;
        CP_ASYNC16(sQ + o, Qp + gmo);
    }
    load_kv(0, 0);
    CP_COMMIT();

    float o_acc[8][4];
#pragma unroll
    for (int i = 0; i < 8; i++)
#pragma unroll
        for (int k = 0; k < 4; k++) o_acc[i][k] = 0.f;
    float m0 = -1e30f, m1 = -1e30f, l0 = 0.f, l1 = 0.f;

    for (int j = 0; j < nchunk; j++) {
        const int buf = j & 1;
        __syncthreads();
        if (j + 1 < nchunk) { load_kv(buf ^ 1, j + 1); CP_COMMIT(); CP_WAIT1(); }
        else                { CP_WAIT0(); }
        __syncthreads();

        const uint32_t st = sb + 16384 + buf * KVSTAGE_B;
        const uint32_t stK = st, stV = st + 8192;

        // ---- S = Q K^T (single fp16) ----
        float s[8][4];
#pragma unroll
        for (int i = 0; i < 8; i++)
#pragma unroll
            for (int k = 0; k < 4; k++) s[i][k] = 0.f;

#pragma unroll
        for (int ks = 0; ks < 4; ks++) {
            uint32_t qf[4];
            uint32_t oA = FSW(w * 16 + (lane & 15), ks * 2 + (lane >> 4));
            LDSM_X4(qf[0], qf[1], qf[2], qf[3], sQ + oA);
#pragma unroll
            for (int nfp = 0; nfp < 4; nfp++) {
                uint32_t oB = FSW(nfp * 16 + ((lane >> 4) & 1) * 8 + (lane & 7),
                                  ks * 2 + ((lane >> 3) & 1));
                uint32_t bh[4];
                LDSM_X4(bh[0], bh[1], bh[2], bh[3], stK + oB);
#pragma unroll
                for (int sub = 0; sub < 2; sub++) {
                    int nf = nfp * 2 + sub;
                    MMA_FP16(s[nf], qf, bh[sub * 2], bh[sub * 2 + 1]);
                }
            }
        }

        // ---- scale + causal mask ----
        const float scale = 0.125f;   // 1/sqrt(64)
        const int rg = qi * 128 + w * 16 + (lane >> 2);
        const int cb = j * 64 + (lane & 3) * 2;
        if (j >= 2 * qi) {
#pragma unroll
            for (int nf = 0; nf < 8; nf++) {
                int c0 = cb + nf * 8;
                s[nf][0] = (c0     <= rg    ) ? s[nf][0] * scale : -1e30f;
                s[nf][1] = (c0 + 1 <= rg    ) ? s[nf][1] * scale : -1e30f;
                s[nf][2] = (c0     <= rg + 8) ? s[nf][2] * scale : -1e30f;
                s[nf][3] = (c0 + 1 <= rg + 8) ? s[nf][3] * scale : -1e30f;
            }
        } else {
#pragma unroll
            for (int nf = 0; nf < 8; nf++)
#pragma unroll
                for (int k = 0; k < 4; k++) s[nf][k] *= scale;
        }

        // ---- online softmax ----
        float mx0 = s[0][0], mx1 = s[0][2];
#pragma unroll
        for (int nf = 0; nf < 8; nf++) {
            mx0 = fmaxf(mx0, fmaxf(s[nf][0], s[nf][1]));
            mx1 = fmaxf(mx1, fmaxf(s[nf][2], s[nf][3]));
        }
        mx0 = fmaxf(mx0, __shfl_xor_sync(0xffffffffu, mx0, 1));
        mx0 = fmaxf(mx0, __shfl_xor_sync(0xffffffffu, mx0, 2));
        mx1 = fmaxf(mx1, __shfl_xor_sync(0xffffffffu, mx1, 1));
        mx1 = fmaxf(mx1, __shfl_xor_sync(0xffffffffu, mx1, 2));

        float mn0 = fmaxf(m0, mx0), mn1 = fmaxf(m1, mx1);
        float cr0 = __expf(m0 - mn0), cr1 = __expf(m1 - mn1);
        m0 = mn0; m1 = mn1;

        float sum0 = 0.f, sum1 = 0.f;
#pragma unroll
        for (int nf = 0; nf < 8; nf++) {
            s[nf][0] = __expf(s[nf][0] - mn0); sum0 += s[nf][0];
            s[nf][1] = __expf(s[nf][1] - mn0); sum0 += s[nf][1];
            s[nf][2] = __expf(s[nf][2] - mn1); sum1 += s[nf][2];
            s[nf][3] = __expf(s[nf][3] - mn1); sum1 += s[nf][3];
        }
        sum0 += __shfl_xor_sync(0xffffffffu, sum0, 1);
        sum0 += __shfl_xor_sync(0xffffffffu, sum0, 2);
        sum1 += __shfl_xor_sync(0xffffffffu, sum1, 1);
        sum1 += __shfl_xor_sync(0xffffffffu, sum1, 2);
        l0 = l0 * cr0 + sum0;
        l1 = l1 * cr1 + sum1;

#pragma unroll
        for (int nf = 0; nf < 8; nf++) {
            o_acc[nf][0] *= cr0; o_acc[nf][1] *= cr0;
            o_acc[nf][2] *= cr1; o_acc[nf][3] *= cr1;
        }

        // ---- O += P V (single fp16) ----
#pragma unroll
        for (int ks = 0; ks < 4; ks++) {
            uint32_t pa[4];
            pa[0] = pack_h2(s[2 * ks][0],     s[2 * ks][1]);
            pa[1] = pack_h2(s[2 * ks][2],     s[2 * ks][3]);
            pa[2] = pack_h2(s[2 * ks + 1][0], s[2 * ks + 1][1]);
            pa[3] = pack_h2(s[2 * ks + 1][2], s[2 * ks + 1][3]);
#pragma unroll
            for (int nfp = 0; nfp < 4; nfp++) {
                uint32_t oV = FSW(ks * 16 + ((lane >> 3) & 1) * 8 + (lane & 7),
                                  nfp * 2 + (lane >> 4));
                uint32_t vf[4];
                LDSM_X4_T(vf[0], vf[1], vf[2], vf[3], stV + oV);
#pragma unroll
                for (int sub = 0; sub < 2; sub++) {
                    int nf = nfp * 2 + sub;
                    MMA_FP16(o_acc[nf], pa, vf[sub * 2], vf[sub * 2 + 1]);
                }
            }
        }
    }

    // ---- epilogue: normalize + fp16 single write ----
    const float inv0 = 1.f / l0, inv1 = 1.f / l1;
    const size_t row0 = (size_t)b * S_LEN + qi * 128 + w * 16 + (lane >> 2);
    const int colb = h * 64 + (lane & 3) * 2;
#pragma unroll
    for (int nf = 0; nf < 8; nf++) {
        int col = colb + nf * 8;
        *(uint32_t*)(g_a16 + row0 * DM + col) =
            pack_h2(o_acc[nf][0] * inv0, o_acc[nf][1] * inv0);
        *(uint32_t*)(g_a16 + (row0 + 8) * DM + col) =
            pack_h2(o_acc[nf][2] * inv1, o_acc[nf][3] * inv1);
    }
}

// ---------------------------------------------------------------------------
extern "C" void kernel_launch(void* const* d_in, const int* in_sizes, int n_in,
                              void* d_out, int out_size)
{
    (void)in_sizes; (void)n_in; (void)out_size;
    const float* x  = (const float*)d_in[0];
    const float* qw = (const float*)d_in[1];
    const float* kw = (const float*)d_in[2];
    const float* vw = (const float*)d_in[3];
    const float* ow = (const float*)d_in[4];
    float* out = (float*)d_out;

    cudaFuncSetAttribute(gemm_h, cudaFuncAttributeMaxDynamicSharedMemorySize, GEMM_SMEM);
    cudaFuncSetAttribute(flash_mma, cudaFuncAttributeMaxDynamicSharedMemorySize, FA_SMEM);

    __half *x16, *wh16, *wl16, *h16, *a16;
    cudaGetSymbolAddress((void**)&x16, g_x16);
    cudaGetSymbolAddress((void**)&wh16, g_wh16);
    cudaGetSymbolAddress((void**)&wl16, g_wl16);
    cudaGetSymbolAddress((void**)&h16, g_h16);
    cudaGetSymbolAddress((void**)&a16, g_a16);

    const int nx4 = MROWS * DM / 4;
    const int nw4 = DM * DM / 4;

    // 1) convert: x -> fp16; 4 weights -> fp16 hi/lo (z-fused)
    cvt_h<<<(nx4 + 255) / 256, 256>>>(x, x16, nx4);
    dim3 gw((nw4 + 255) / 256, 1, 4);
    cvt_w4<<<gw, 256>>>(qw, kw, vw, ow, wh16, wl16, nw4);

    // 2) QKV projection (2-product) -> Q|K|V fp16 single
    dim3 gq(DM / 128, MROWS / 128, 3);
    gemm_h<<<gq, 256, GEMM_SMEM>>>(x16, wh16, wl16, nullptr, h16,
                                   (long)DM * DM, (long)MN);

    // 3) causal flash attention -> att fp16 single
    dim3 ga(S_LEN / 128, BATCHN * NHEAD, 1);
    flash_mma<<<ga, 256, FA_SMEM>>>();

    // 4) O projection (2-product) -> fp32 final output
    dim3 go(DM / 128, MROWS / 128, 1);
    gemm_h<<<go, 256, GEMM_SMEM>>>(a16, wh16 + 3ul * DM * DM, wl16 + 3ul * DM * DM,
                                   out, nullptr, 0L, 0L);
}

// round 17
// speedup vs baseline: 6.5716x; 1.1686x over previous
#include <cuda_runtime.h>
#include <cuda_fp16.h>
#include <cstdint>
#include <math.h>

// Problem constants
#define S_LEN 2048
#define BATCHN 2
#define DM 1024
#define NHEAD 16
#define DHEAD 64
#define MROWS (BATCHN * S_LEN)   // 4096
#define MN ((size_t)MROWS * DM)

// ---------------------------------------------------------------------------
// Scratch (device globals: allocation-free rule)
// ---------------------------------------------------------------------------
__device__ __half g_h16[(size_t)3 * MN];        // Q | K | V  (fp16)
__device__ __half g_x16[MN];                    // x truncated fp16
__device__ __half g_wh16[(size_t)4 * DM * DM];  // q,k,v,o weight hi
__device__ __half g_wl16[(size_t)4 * DM * DM];  // q,k,v,o weight lo
__device__ __half g_a16[MN];                    // attention out fp16

// ---------------------------------------------------------------------------
// PTX helpers — sm_80+ only (plain compute_103 target: no tcgen05)
// ---------------------------------------------------------------------------
__device__ __forceinline__ uint32_t smem_u32(const void* p) {
    uint32_t a;
    asm("{ .reg .u64 t; cvta.to.shared.u64 t, %1; cvt.u32.u64 %0, t; }" : "=r"(a) : "l"(p));
    return a;
}

#define LDSM_X4(r0, r1, r2, r3, addr) \
    asm volatile("ldmatrix.sync.aligned.m8n8.x4.shared.b16 {%0,%1,%2,%3}, [%4];" \
                 : "=r"(r0), "=r"(r1), "=r"(r2), "=r"(r3) : "r"(addr))

#define LDSM_X4_T(r0, r1, r2, r3, addr) \
    asm volatile("ldmatrix.sync.aligned.m8n8.x4.trans.shared.b16 {%0,%1,%2,%3}, [%4];" \
                 : "=r"(r0), "=r"(r1), "=r"(r2), "=r"(r3) : "r"(addr))

#define MMA_FP16(c, a, b0, b1) \
    asm volatile("mma.sync.aligned.m16n8k16.row.col.f32.f16.f16.f32 " \
                 "{%0,%1,%2,%3}, {%4,%5,%6,%7}, {%8,%9}, {%0,%1,%2,%3};" \
                 : "+f"((c)[0]), "+f"((c)[1]), "+f"((c)[2]), "+f"((c)[3]) \
                 : "r"((a)[0]), "r"((a)[1]), "r"((a)[2]), "r"((a)[3]), "r"(b0), "r"(b1))

#define CP_ASYNC16(saddr, gaddr) \
    asm volatile("cp.async.cg.shared.global [%0], [%1], 16;" :: "r"(saddr), "l"(gaddr))
#define CP_COMMIT() asm volatile("cp.async.commit_group;" ::: "memory")
#define CP_WAIT0()  asm volatile("cp.async.wait_group 0;" ::: "memory")
#define CP_WAIT1()  asm volatile("cp.async.wait_group 1;" ::: "memory")

__device__ __forceinline__ uint32_t pack_h2(float x, float y) {
    __half2 h = __floats2half2_rn(x, y);
    return *(uint32_t*)&h;
}
__device__ __forceinline__ void split2h(float x, float y, uint32_t& hi, uint32_t& lo) {
    __half2 h = __floats2half2_rn(x, y);
    __half2 l = __floats2half2_rn(x - __half2float(h.x), y - __half2float(h.y));
    hi = *(uint32_t*)&h;
    lo = *(uint32_t*)&l;
}

// 128-byte-row swizzle (shared by flash and BK=64 GEMM; proven)
#define FSW(row, c16) ((uint32_t)((row) * 128 + ((((c16) ^ ((row) & 7))) << 4)))

// ---------------------------------------------------------------------------
// fp32 -> fp16 truncate (x)
// ---------------------------------------------------------------------------
__global__ void cvt_h(const float* __restrict__ src, __half* __restrict__ dst, int n4)
{
    int i = blockIdx.x * blockDim.x + threadIdx.x;
    if (i >= n4) return;
    float4 v = ((const float4*)src)[i];
    ((uint32_t*)dst)[2 * i + 0] = pack_h2(v.x, v.y);
    ((uint32_t*)dst)[2 * i + 1] = pack_h2(v.z, v.w);
}

// fp32 -> fp16 hi/lo split, 4 weight tensors via z
__global__ void cvt_w4(const float* __restrict__ s0, const float* __restrict__ s1,
                       const float* __restrict__ s2, const float* __restrict__ s3,
                       __half* __restrict__ hi, __half* __restrict__ lo, int n4)
{
    int i = blockIdx.x * blockDim.x + threadIdx.x;
    if (i >= n4) return;
    int z = blockIdx.z;
    const float* src = (z == 0) ? s0 : (z == 1) ? s1 : (z == 2) ? s2 : s3;
    __half* h = hi + (size_t)z * DM * DM;
    __half* l = lo + (size_t)z * DM * DM;
    float4 v = ((const float4*)src)[i];
    uint32_t h0, l0, h1, l1;
    split2h(v.x, v.y, h0, l0);
    split2h(v.z, v.w, h1, l1);
    ((uint32_t*)h)[2 * i + 0] = h0;
    ((uint32_t*)h)[2 * i + 1] = h1;
    ((uint32_t*)l)[2 * i + 0] = l0;
    ((uint32_t*)l)[2 * i + 1] = l1;
}

// ---------------------------------------------------------------------------
// mma.sync fp16 NT GEMM, BK=64 (128B rows, FSW swizzle — flash-proven layout).
// C = A * (W_h + W_l), A single fp16, fp32 accumulate. 2-stage cp.async.
// Epilogue: Cf -> fp32, else fp16 single to Ch.
// ---------------------------------------------------------------------------
#define GBK 64
#define GTILE_B (128 * GBK * 2)            // 16384 bytes per tile
#define GSTAGE_B (3 * GTILE_B)             // A|Wh|Wl = 49152
#define GEMM_SMEM (2 * GSTAGE_B)           // 98304
#define GNCHUNK (DM / GBK)                 // 16

__global__ void __launch_bounds__(256, 2)
gemm_h(const __half* __restrict__ Ah,
       const __half* __restrict__ Wh, const __half* __restrict__ Wl,
       float* __restrict__ Cf, __half* __restrict__ Ch,
       long wstride, long cstride)
{
    extern __shared__ __align__(16) char smem[];
    const uint32_t sb = smem_u32(smem);
    const int tid = threadIdx.x;
    const int wid = tid >> 5, lane = tid & 31;
    const int z = blockIdx.z;
    const __half* wh = Wh + (size_t)z * wstride;
    const __half* wl = Wl + (size_t)z * wstride;
    const int m0 = blockIdx.y * 128;
    const int n0 = blockIdx.x * 128;

    const int wm = wid & 3;
    const int wn = wid >> 2;

    float acc[2][8][4];
#pragma unroll
    for (int i = 0; i < 2; i++)
#pragma unroll
        for (int j = 0; j < 8; j++)
#pragma unroll
            for (int k = 0; k < 4; k++) acc[i][j][k] = 0.f;

    // load mapping: tile has 128 rows x 8 c16 = 1024 sixteen-byte units;
    // idx = tid + i*256, i<4: row = idx>>3, c16 = idx&7 (same as flash load_kv)
    auto load_chunk = [&](int s, int c) {
        const uint32_t st = sb + s * GSTAGE_B;
        const int k0 = c * GBK;
#pragma unroll
        for (int i = 0; i < 4; i++) {
            int idx = tid + i * 256;
            int row = idx >> 3, c16 = idx & 7;
            uint32_t o = FSW(row, c16);
            size_t ga = (size_t)(m0 + row) * DM + k0 + c16 * 8;
            size_t gb = (size_t)(n0 + row) * DM + k0 + c16 * 8;
            CP_ASYNC16(st + 0 * GTILE_B + o, Ah + ga);
            CP_ASYNC16(st + 1 * GTILE_B + o, wh + gb);
            CP_ASYNC16(st + 2 * GTILE_B + o, wl + gb);
        }
    };

    load_chunk(0, 0); CP_COMMIT();
    load_chunk(1, 1); CP_COMMIT();

    for (int c = 0; c < GNCHUNK; c++) {
        const int buf = c & 1;
        CP_WAIT1();
        __syncthreads();

        const uint32_t st = sb + buf * GSTAGE_B;
        const uint32_t sA = st, sBh = st + GTILE_B, sBl = st + 2 * GTILE_B;

#pragma unroll
        for (int ks = 0; ks < 4; ks++) {
            uint32_t ah[2][4];
#pragma unroll
            for (int mf = 0; mf < 2; mf++) {
                uint32_t o = FSW(wm * 32 + mf * 16 + (lane & 15), ks * 2 + (lane >> 4));
                LDSM_X4(ah[mf][0], ah[mf][1], ah[mf][2], ah[mf][3], sA + o);
            }
#pragma unroll
            for (int nfp = 0; nfp < 4; nfp++) {
                uint32_t o = FSW(wn * 64 + nfp * 16 + ((lane >> 4) & 1) * 8 + (lane & 7),
                                 ks * 2 + ((lane >> 3) & 1));
                uint32_t bh[4], bl[4];
                LDSM_X4(bh[0], bh[1], bh[2], bh[3], sBh + o);
                LDSM_X4(bl[0], bl[1], bl[2], bl[3], sBl + o);
#pragma unroll
                for (int sub = 0; sub < 2; sub++) {
                    int nf = nfp * 2 + sub;
                    uint32_t h0 = bh[sub * 2], h1 = bh[sub * 2 + 1];
                    uint32_t l0 = bl[sub * 2], l1 = bl[sub * 2 + 1];
#pragma unroll
                    for (int mf = 0; mf < 2; mf++) {
                        MMA_FP16(acc[mf][nf], ah[mf], h0, h1);
                        MMA_FP16(acc[mf][nf], ah[mf], l0, l1);
                    }
                }
            }
        }
        __syncthreads();
        if (c + 2 < GNCHUNK) load_chunk(buf, c + 2);
        CP_COMMIT();
    }

    const int g = lane >> 2, t = lane & 3;
    if (Cf) {
        float* C = Cf + (size_t)z * cstride;
#pragma unroll
        for (int mf = 0; mf < 2; mf++)
#pragma unroll
            for (int nf = 0; nf < 8; nf++) {
                int row = m0 + wm * 32 + mf * 16 + g;
                int col = n0 + wn * 64 + nf * 8 + 2 * t;
                float* p0 = C + (size_t)row * DM + col;
                float* p1 = C + (size_t)(row + 8) * DM + col;
                p0[0] = acc[mf][nf][0]; p0[1] = acc[mf][nf][1];
                p1[0] = acc[mf][nf][2]; p1[1] = acc[mf][nf][3];
            }
    } else {
        __half* CH = Ch + (size_t)z * cstride;
#pragma unroll
        for (int mf = 0; mf < 2; mf++)
#pragma unroll
            for (int nf = 0; nf < 8; nf++) {
                int row = m0 + wm * 32 + mf * 16 + g;
                int col = n0 + wn * 64 + nf * 8 + 2 * t;
                *(uint32_t*)(CH + (size_t)row * DM + col) =
                    pack_h2(acc[mf][nf][0], acc[mf][nf][1]);
                *(uint32_t*)(CH + (size_t)(row + 8) * DM + col) =
                    pack_h2(acc[mf][nf][2], acc[mf][nf][3]);
            }
    }
}

// ---------------------------------------------------------------------------
// Tensor-core causal flash attention — single fp16, fp32 accum.
// Q tile 128 rows, KV tile 64, 8 warps. Q fragments hoisted to registers
// (loaded once at j==0). Softmax in log2 domain (exp2f, folded scale).
// Smem: Q 16KB + 2-stage {K 8K, V 8K} = 48KB dynamic.
// ---------------------------------------------------------------------------
#define KVSTAGE_B 16384
#define FA_SMEM (16384 + 2 * KVSTAGE_B)   // 49152

__global__ void __launch_bounds__(256, 2)
flash_mma(void)
{
    extern __shared__ __align__(16) char fsm[];
    const uint32_t sb = smem_u32(fsm);
    const uint32_t sQ = sb;

    const int qi = (gridDim.x - 1) - blockIdx.x;   // big tiles first
    const int b  = blockIdx.y >> 4;
    const int h  = blockIdx.y & 15;

    const int tid = threadIdx.x;
    const int w = tid >> 5, lane = tid & 31;

    const size_t base = (size_t)b * S_LEN * DM + h * DHEAD;
    const __half* Qp = g_h16 + base;
    const __half* Kp = g_h16 + MN + base;
    const __half* Vp = g_h16 + 2 * MN + base;

    const int nchunk = 2 * qi + 2;    // KV chunks of 64 rows

    auto load_kv = [&](int stage, int j) {
        const uint32_t st = sb + 16384 + stage * KVSTAGE_B;
#pragma unroll
        for (int i = 0; i < 2; i++) {
            int idx = tid + i * 256;          // 0..511
            int row = idx >> 3, c16 = idx & 7;
            uint32_t o = FSW(row, c16);
            size_t gmo = (size_t)(j * 64 + row) * DM + c16 * 8;
            CP_ASYNC16(st + 0    + o, Kp + gmo);
            CP_ASYNC16(st + 8192 + o, Vp + gmo);
        }
    };

    // prologue: Q tile (128 rows x 64 fp16 = 16KB) + KV stage 0
#pragma unroll
    for (int i = 0; i < 4; i++) {
        int idx = tid + i * 256;              // 0..1023
        int row = idx >> 3, c16 = idx & 7;
        uint32_t o = FSW(row, c16);
        size_t gmo = (size_t)(qi * 128 + row) * DM + c16 * 8;
        CP_ASYNC16(sQ + o, Qp + gmo);
    }
    load_kv(0, 0);
    CP_COMMIT();

    float o_acc[8][4];
#pragma unroll
    for (int i = 0; i < 8; i++)
#pragma unroll
        for (int k = 0; k < 4; k++) o_acc[i][k] = 0.f;
    float m0 = -1e30f, m1 = -1e30f, l0 = 0.f, l1 = 0.f;

    uint32_t qreg[4][4];   // Q fragments, hoisted (loaded at j==0)

    for (int j = 0; j < nchunk; j++) {
        const int buf = j & 1;
        __syncthreads();
        if (j + 1 < nchunk) { load_kv(buf ^ 1, j + 1); CP_COMMIT(); CP_WAIT1(); }
        else                { CP_WAIT0(); }
        __syncthreads();

        if (j == 0) {
#pragma unroll
            for (int ks = 0; ks < 4; ks++) {
                uint32_t oA = FSW(w * 16 + (lane & 15), ks * 2 + (lane >> 4));
                LDSM_X4(qreg[ks][0], qreg[ks][1], qreg[ks][2], qreg[ks][3], sQ + oA);
            }
        }

        const uint32_t st = sb + 16384 + buf * KVSTAGE_B;
        const uint32_t stK = st, stV = st + 8192;

        // ---- S = Q K^T (single fp16) ----
        float s[8][4];
#pragma unroll
        for (int i = 0; i < 8; i++)
#pragma unroll
            for (int k = 0; k < 4; k++) s[i][k] = 0.f;

#pragma unroll
        for (int ks = 0; ks < 4; ks++) {
#pragma unroll
            for (int nfp = 0; nfp < 4; nfp++) {
                uint32_t oB = FSW(nfp * 16 + ((lane >> 4) & 1) * 8 + (lane & 7),
                                  ks * 2 + ((lane >> 3) & 1));
                uint32_t bh[4];
                LDSM_X4(bh[0], bh[1], bh[2], bh[3], stK + oB);
#pragma unroll
                for (int sub = 0; sub < 2; sub++) {
                    int nf = nfp * 2 + sub;
                    MMA_FP16(s[nf], qreg[ks], bh[sub * 2], bh[sub * 2 + 1]);
                }
            }
        }

        // ---- scale (log2 domain) + causal mask ----
        const float scl2 = 0.18033688f;   // 0.125 * log2(e)
        const int rg = qi * 128 + w * 16 + (lane >> 2);
        const int cb = j * 64 + (lane & 3) * 2;
        if (j >= 2 * qi) {
#pragma unroll
            for (int nf = 0; nf < 8; nf++) {
                int c0 = cb + nf * 8;
                s[nf][0] = (c0     <= rg    ) ? s[nf][0] * scl2 : -1e30f;
                s[nf][1] = (c0 + 1 <= rg    ) ? s[nf][1] * scl2 : -1e30f;
                s[nf][2] = (c0     <= rg + 8) ? s[nf][2] * scl2 : -1e30f;
                s[nf][3] = (c0 + 1 <= rg + 8) ? s[nf][3] * scl2 : -1e30f;
            }
        } else {
#pragma unroll
            for (int nf = 0; nf < 8; nf++)
#pragma unroll
                for (int k = 0; k < 4; k++) s[nf][k] *= scl2;
        }

        // ---- online softmax (log2 domain; exp2f = bare EX2) ----
        float mx0 = s[0][0], mx1 = s[0][2];
#pragma unroll
        for (int nf = 0; nf < 8; nf++) {
            mx0 = fmaxf(mx0, fmaxf(s[nf][0], s[nf][1]));
            mx1 = fmaxf(mx1, fmaxf(s[nf][2], s[nf][3]));
        }
        mx0 = fmaxf(mx0, __shfl_xor_sync(0xffffffffu, mx0, 1));
        mx0 = fmaxf(mx0, __shfl_xor_sync(0xffffffffu, mx0, 2));
        mx1 = fmaxf(mx1, __shfl_xor_sync(0xffffffffu, mx1, 1));
        mx1 = fmaxf(mx1, __shfl_xor_sync(0xffffffffu, mx1, 2));

        float mn0 = fmaxf(m0, mx0), mn1 = fmaxf(m1, mx1);
        float cr0 = exp2f(m0 - mn0), cr1 = exp2f(m1 - mn1);
        m0 = mn0; m1 = mn1;

        float sum0 = 0.f, sum1 = 0.f;
#pragma unroll
        for (int nf = 0; nf < 8; nf++) {
            s[nf][0] = exp2f(s[nf][0] - mn0); sum0 += s[nf][0];
            s[nf][1] = exp2f(s[nf][1] - mn0); sum0 += s[nf][1];
            s[nf][2] = exp2f(s[nf][2] - mn1); sum1 += s[nf][2];
            s[nf][3] = exp2f(s[nf][3] - mn1); sum1 += s[nf][3];
        }
        sum0 += __shfl_xor_sync(0xffffffffu, sum0, 1);
        sum0 += __shfl_xor_sync(0xffffffffu, sum0, 2);
        sum1 += __shfl_xor_sync(0xffffffffu, sum1, 1);
        sum1 += __shfl_xor_sync(0xffffffffu, sum1, 2);
        l0 = l0 * cr0 + sum0;
        l1 = l1 * cr1 + sum1;

#pragma unroll
        for (int nf = 0; nf < 8; nf++) {
            o_acc[nf][0] *= cr0; o_acc[nf][1] *= cr0;
            o_acc[nf][2] *= cr1; o_acc[nf][3] *= cr1;
        }

        // ---- O += P V (single fp16) ----
#pragma unroll
        for (int ks = 0; ks < 4; ks++) {
            uint32_t pa[4];
            pa[0] = pack_h2(s[2 * ks][0],     s[2 * ks][1]);
            pa[1] = pack_h2(s[2 * ks][2],     s[2 * ks][3]);
            pa[2] = pack_h2(s[2 * ks + 1][0], s[2 * ks + 1][1]);
            pa[3] = pack_h2(s[2 * ks + 1][2], s[2 * ks + 1][3]);
#pragma unroll
            for (int nfp = 0; nfp < 4; nfp++) {
                uint32_t oV = FSW(ks * 16 + ((lane >> 3) & 1) * 8 + (lane & 7),
                                  nfp * 2 + (lane >> 4));
                uint32_t vf[4];
                LDSM_X4_T(vf[0], vf[1], vf[2], vf[3], stV + oV);
#pragma unroll
                for (int sub = 0; sub < 2; sub++) {
                    int nf = nfp * 2 + sub;
                    MMA_FP16(o_acc[nf], pa, vf[sub * 2], vf[sub * 2 + 1]);
                }
            }
        }
    }

    // ---- epilogue: normalize + fp16 single write ----
    const float inv0 = 1.f / l0, inv1 = 1.f / l1;
    const size_t row0 = (size_t)b * S_LEN + qi * 128 + w * 16 + (lane >> 2);
    const int colb = h * 64 + (lane & 3) * 2;
#pragma unroll
    for (int nf = 0; nf < 8; nf++) {
        int col = colb + nf * 8;
        *(uint32_t*)(g_a16 + row0 * DM + col) =
            pack_h2(o_acc[nf][0] * inv0, o_acc[nf][1] * inv0);
        *(uint32_t*)(g_a16 + (row0 + 8) * DM + col) =
            pack_h2(o_acc[nf][2] * inv1, o_acc[nf][3] * inv1);
    }
}

// ---------------------------------------------------------------------------
extern "C" void kernel_launch(void* const* d_in, const int* in_sizes, int n_in,
                              void* d_out, int out_size)
{
    (void)in_sizes; (void)n_in; (void)out_size;
    const float* x  = (const float*)d_in[0];
    const float* qw = (const float*)d_in[1];
    const float* kw = (const float*)d_in[2];
    const float* vw = (const float*)d_in[3];
    const float* ow = (const float*)d_in[4];
    float* out = (float*)d_out;

    cudaFuncSetAttribute(gemm_h, cudaFuncAttributeMaxDynamicSharedMemorySize, GEMM_SMEM);
    cudaFuncSetAttribute(flash_mma, cudaFuncAttributeMaxDynamicSharedMemorySize, FA_SMEM);

    __half *x16, *wh16, *wl16, *h16, *a16;
    cudaGetSymbolAddress((void**)&x16, g_x16);
    cudaGetSymbolAddress((void**)&wh16, g_wh16);
    cudaGetSymbolAddress((void**)&wl16, g_wl16);
    cudaGetSymbolAddress((void**)&h16, g_h16);
    cudaGetSymbolAddress((void**)&a16, g_a16);

    const int nx4 = MROWS * DM / 4;
    const int nw4 = DM * DM / 4;

    // 1) convert: x -> fp16; 4 weights -> fp16 hi/lo (z-fused)
    cvt_h<<<(nx4 + 255) / 256, 256>>>(x, x16, nx4);
    dim3 gw((nw4 + 255) / 256, 1, 4);
    cvt_w4<<<gw, 256>>>(qw, kw, vw, ow, wh16, wl16, nw4);

    // 2) QKV projection (2-product, BK=64) -> Q|K|V fp16 single
    dim3 gq(DM / 128, MROWS / 128, 3);
    gemm_h<<<gq, 256, GEMM_SMEM>>>(x16, wh16, wl16, nullptr, h16,
                                   (long)DM * DM, (long)MN);

    // 3) causal flash attention -> att fp16 single
    dim3 ga(S_LEN / 128, BATCHN * NHEAD, 1);
    flash_mma<<<ga, 256, FA_SMEM>>>();

    // 4) O projection (2-product, BK=64) -> fp32 final output
    dim3 go(DM / 128, MROWS / 128, 1);
    gemm_h<<<go, 256, GEMM_SMEM>>>(a16, wh16 + 3ul * DM * DM, wl16 + 3ul * DM * DM,
                                   out, nullptr, 0L, 0L);
}